// round 9
// baseline (speedup 1.0000x reference)
#include <cuda_runtime.h>
#include <math.h>
#include <stdint.h>

#define F 256
#define NN 4096
#define TT 8
#define PAD 20

// ---------------- scratch (no allocations allowed) ----------------
__device__ float g_sn[2];
__device__ float g_Q[2 * 2 * F * F];   // [layer][pingpong][F*F]
__device__ float g_P[7 * F * F];       // P[t] = A[t][0:256,:] @ X[t]
__device__ float g_E[F * F];           // layer-1 h_top
__device__ float g_tv0[TT * F];        // layer-0 tanh(score) for all t
__device__ float g_tv[F];              // layer-1 tanh(score), current step
__device__ float g_upd[F * F];
__device__ float g_rq[F * F];
__device__ float g_whz[F * F];
__device__ float g_Yt[F * NN];         // transposed Y: [256, 4096] k-major B operand
__device__ float g_h1[NN * F];
__device__ float g_Xt[7 * F * NN];     // transposed X per t (B operand for P GEMMs)

// =================== tf32 split helpers ===================
__device__ __forceinline__ void split2(float v, uint32_t& hi, uint32_t& lo) {
    uint32_t u = __float_as_uint(v) & 0xffffe000u;
    hi = u;
    lo = __float_as_uint(v - __uint_as_float(u));
}

__device__ __forceinline__ void mma_tf32(float* d, const uint32_t* a, const uint32_t* b) {
    asm volatile(
        "mma.sync.aligned.m16n8k8.row.col.f32.tf32.tf32.f32 "
        "{%0,%1,%2,%3}, {%4,%5,%6,%7}, {%8,%9}, {%0,%1,%2,%3};\n"
        : "+f"(d[0]), "+f"(d[1]), "+f"(d[2]), "+f"(d[3])
        : "r"(a[0]), "r"(a[1]), "r"(a[2]), "r"(a[3]), "r"(b[0]), "r"(b[1]));
}

// ============ tf32 3x-split GEMM: C[.,256] = [relu](A[M,K] @ Bt[256,K]^T) =====
// CTA tile M=128, N=64, kc=16; 8 warps (4m x 2n), warp tile 32x32.
__global__ void __launch_bounds__(256) tf32_gemm_kernel(
    const float* __restrict__ A, size_t strideA,
    const float* __restrict__ Bt, size_t strideB,
    float* __restrict__ C, size_t strideC,
    int K, int do_relu) {
    __shared__ float As[2][128][20];
    __shared__ float Bs[2][64][20];

    const float* Ap = A + strideA * blockIdx.z;
    const float* Bp = Bt + strideB * blockIdx.z;
    float* Cp = C + strideC * blockIdx.z;

    const int bm = blockIdx.y * 128;
    const int bn = blockIdx.x * 64;
    const int tid = threadIdx.x;
    const int wid = tid >> 5, lane = tid & 31;
    const int wm = (wid & 3) * 32;
    const int wn = (wid >> 2) * 32;
    const int gid = lane >> 2, tig = lane & 3;

    const int ar = tid >> 1;
    const int ak = (tid & 1) * 8;
    const int br = tid >> 2;
    const int bk = (tid & 3) * 4;

    float acc[2][4][4];
#pragma unroll
    for (int i = 0; i < 2; i++)
#pragma unroll
        for (int j = 0; j < 4; j++)
#pragma unroll
            for (int r = 0; r < 4; r++) acc[i][j][r] = 0.f;

    const int ntiles = K >> 4;

    float4 a0v = *(const float4*)(Ap + (size_t)(bm + ar) * K + ak);
    float4 a1v = *(const float4*)(Ap + (size_t)(bm + ar) * K + ak + 4);
    float4 bv = *(const float4*)(Bp + (size_t)(bn + br) * K + bk);
    *(float4*)&As[0][ar][ak] = a0v;
    *(float4*)&As[0][ar][ak + 4] = a1v;
    *(float4*)&Bs[0][br][bk] = bv;
    __syncthreads();

    for (int tile = 0; tile < ntiles; tile++) {
        const int buf = tile & 1;
        if (tile + 1 < ntiles) {
            const int k0 = (tile + 1) << 4;
            a0v = *(const float4*)(Ap + (size_t)(bm + ar) * K + k0 + ak);
            a1v = *(const float4*)(Ap + (size_t)(bm + ar) * K + k0 + ak + 4);
            bv = *(const float4*)(Bp + (size_t)(bn + br) * K + k0 + bk);
        }
#pragma unroll
        for (int ks = 0; ks < 2; ks++) {
            const int kb = ks * 8;
            uint32_t ahi[2][4], alo[2][4];
#pragma unroll
            for (int mf = 0; mf < 2; mf++) {
                const int r = wm + mf * 16 + gid;
                split2(As[buf][r][kb + tig], ahi[mf][0], alo[mf][0]);
                split2(As[buf][r + 8][kb + tig], ahi[mf][1], alo[mf][1]);
                split2(As[buf][r][kb + tig + 4], ahi[mf][2], alo[mf][2]);
                split2(As[buf][r + 8][kb + tig + 4], ahi[mf][3], alo[mf][3]);
            }
            uint32_t bhi[4][2], blo[4][2];
#pragma unroll
            for (int nf = 0; nf < 4; nf++) {
                const int n = wn + nf * 8 + gid;
                split2(Bs[buf][n][kb + tig], bhi[nf][0], blo[nf][0]);
                split2(Bs[buf][n][kb + tig + 4], bhi[nf][1], blo[nf][1]);
            }
#pragma unroll
            for (int mf = 0; mf < 2; mf++)
#pragma unroll
                for (int nf = 0; nf < 4; nf++) {
                    mma_tf32(acc[mf][nf], ahi[mf], bhi[nf]);
                    mma_tf32(acc[mf][nf], ahi[mf], blo[nf]);
                    mma_tf32(acc[mf][nf], alo[mf], bhi[nf]);
                }
        }
        __syncthreads();
        if (tile + 1 < ntiles) {
            const int nb = (tile + 1) & 1;
            *(float4*)&As[nb][ar][ak] = a0v;
            *(float4*)&As[nb][ar][ak + 4] = a1v;
            *(float4*)&Bs[nb][br][bk] = bv;
            __syncthreads();
        }
    }

#pragma unroll
    for (int mf = 0; mf < 2; mf++)
#pragma unroll
        for (int nf = 0; nf < 4; nf++) {
            const int row = bm + wm + mf * 16 + gid;
            const int col = bn + wn + nf * 8 + tig * 2;
            float v0 = acc[mf][nf][0], v1 = acc[mf][nf][1];
            float v2 = acc[mf][nf][2], v3 = acc[mf][nf][3];
            if (do_relu) {
                v0 = fmaxf(v0, 0.f); v1 = fmaxf(v1, 0.f);
                v2 = fmaxf(v2, 0.f); v3 = fmaxf(v3, 0.f);
            }
            Cp[(size_t)row * F + col] = v0;
            Cp[(size_t)row * F + col + 1] = v1;
            Cp[(size_t)(row + 8) * F + col] = v2;
            Cp[(size_t)(row + 8) * F + col + 1] = v3;
        }
}

// ============ GRU stage 1 (tensor): acc = W @ (tv*E)^T + U @ Q ================
// CTA 64x64, grid (4 m, 4 n, 3 gates), 8 warps (4m x 2n), warp tile 16x32.
__global__ void __launch_bounds__(256) stage1_tc(
    const float* __restrict__ Wz, const float* __restrict__ Uz, const float* __restrict__ bz,
    const float* __restrict__ Wr, const float* __restrict__ Ur, const float* __restrict__ br,
    const float* __restrict__ Wh, const float* __restrict__ bh,
    const float* __restrict__ E, const float* __restrict__ tv,
    const float* __restrict__ Q,
    float* __restrict__ upd, float* __restrict__ rq, float* __restrict__ whz) {
    const int gate = blockIdx.z;
    const float* W = (gate == 0) ? Wz : ((gate == 1) ? Wr : Wh);
    const float* U = (gate == 0) ? Uz : Ur;
    const float* bias = (gate == 0) ? bz : ((gate == 1) ? br : bh);

    __shared__ float Ws[64][PAD];
    __shared__ float Us[64][PAD];
    __shared__ float Es[64][PAD];
    __shared__ float Qs[64][PAD];

    const int bm = blockIdx.x * 64;
    const int bn = blockIdx.y * 64;
    const int tid = threadIdx.x;
    const int wid = tid >> 5, lane = tid & 31;
    const int wm = (wid & 3) * 16;
    const int wn = (wid >> 2) * 32;
    const int gid = lane >> 2, tig = lane & 3;

    const int lr = tid >> 2, lk = (tid & 3) * 4;       // 64x16 tiles
    const int qk = tid >> 4, qn = (tid & 15) * 4;      // Q: 16x64 -> transpose

    const float tvv = tv[bn + lr];

    float acc[4][4];
#pragma unroll
    for (int j = 0; j < 4; j++)
#pragma unroll
        for (int r = 0; r < 4; r++) acc[j][r] = 0.f;

    float4 wv = *(const float4*)(W + (size_t)(bm + lr) * F + lk);
    float4 ev = *(const float4*)(E + (size_t)(bn + lr) * F + lk);
    float4 uv, qv;
    if (gate < 2) {
        uv = *(const float4*)(U + (size_t)(bm + lr) * F + lk);
        qv = *(const float4*)(Q + (size_t)qk * F + bn + qn);
    }

    for (int t16 = 0; t16 < 16; t16++) {
        *(float4*)&Ws[lr][lk] = wv;
        Es[lr][lk] = ev.x * tvv; Es[lr][lk + 1] = ev.y * tvv;
        Es[lr][lk + 2] = ev.z * tvv; Es[lr][lk + 3] = ev.w * tvv;
        if (gate < 2) {
            *(float4*)&Us[lr][lk] = uv;
            Qs[qn][qk] = qv.x; Qs[qn + 1][qk] = qv.y;
            Qs[qn + 2][qk] = qv.z; Qs[qn + 3][qk] = qv.w;
        }
        __syncthreads();
        if (t16 < 15) {
            const int k0 = (t16 + 1) * 16;
            wv = *(const float4*)(W + (size_t)(bm + lr) * F + k0 + lk);
            ev = *(const float4*)(E + (size_t)(bn + lr) * F + k0 + lk);
            if (gate < 2) {
                uv = *(const float4*)(U + (size_t)(bm + lr) * F + k0 + lk);
                qv = *(const float4*)(Q + (size_t)(k0 + qk) * F + bn + qn);
            }
        }
#pragma unroll
        for (int ks = 0; ks < 2; ks++) {
            const int kb = ks * 8;
            // phase W x (tv*E)^T
            {
                uint32_t ahi[4], alo[4];
                split2(Ws[wm + gid][kb + tig], ahi[0], alo[0]);
                split2(Ws[wm + gid + 8][kb + tig], ahi[1], alo[1]);
                split2(Ws[wm + gid][kb + tig + 4], ahi[2], alo[2]);
                split2(Ws[wm + gid + 8][kb + tig + 4], ahi[3], alo[3]);
                uint32_t bhi[4][2], blo[4][2];
#pragma unroll
                for (int nf = 0; nf < 4; nf++) {
                    const int n = wn + nf * 8 + gid;
                    split2(Es[n][kb + tig], bhi[nf][0], blo[nf][0]);
                    split2(Es[n][kb + tig + 4], bhi[nf][1], blo[nf][1]);
                }
#pragma unroll
                for (int nf = 0; nf < 4; nf++) {
                    mma_tf32(acc[nf], ahi, bhi[nf]);
                    mma_tf32(acc[nf], ahi, blo[nf]);
                    mma_tf32(acc[nf], alo, bhi[nf]);
                }
            }
            // phase U x Q
            if (gate < 2) {
                uint32_t ahi[4], alo[4];
                split2(Us[wm + gid][kb + tig], ahi[0], alo[0]);
                split2(Us[wm + gid + 8][kb + tig], ahi[1], alo[1]);
                split2(Us[wm + gid][kb + tig + 4], ahi[2], alo[2]);
                split2(Us[wm + gid + 8][kb + tig + 4], ahi[3], alo[3]);
                uint32_t bhi[4][2], blo[4][2];
#pragma unroll
                for (int nf = 0; nf < 4; nf++) {
                    const int n = wn + nf * 8 + gid;
                    split2(Qs[n][kb + tig], bhi[nf][0], blo[nf][0]);
                    split2(Qs[n][kb + tig + 4], bhi[nf][1], blo[nf][1]);
                }
#pragma unroll
                for (int nf = 0; nf < 4; nf++) {
                    mma_tf32(acc[nf], ahi, bhi[nf]);
                    mma_tf32(acc[nf], ahi, blo[nf]);
                    mma_tf32(acc[nf], alo, bhi[nf]);
                }
            }
        }
        __syncthreads();
    }

#pragma unroll
    for (int nf = 0; nf < 4; nf++) {
        const int row = bm + wm + gid;
        const int col = bn + wn + nf * 8 + tig * 2;
#pragma unroll
        for (int half = 0; half < 2; half++) {
            const int r = row + half * 8;
#pragma unroll
            for (int j = 0; j < 2; j++) {
                const size_t idx = (size_t)r * F + col + j;
                float v = acc[nf][half * 2 + j] + bias[idx];
                if (gate == 0) {
                    upd[idx] = 1.f / (1.f + expf(-v));
                } else if (gate == 1) {
                    rq[idx] = (1.f / (1.f + expf(-v))) * Q[idx];
                } else {
                    whz[idx] = v;
                }
            }
        }
    }
}

// ============ GRU stage 2 (tensor): Qn = (1-u)Q + u*tanh(whz + Uh@rq) =========
// CTA 64x64, grid (4, 4), 8 warps (4m x 2n), warp tile 16x32.
__global__ void __launch_bounds__(256) stage2_tc(
    const float* __restrict__ Uh, const float* __restrict__ Q,
    const float* __restrict__ rq, const float* __restrict__ upd,
    const float* __restrict__ whz, float* __restrict__ Qout) {
    __shared__ float Us[64][PAD];
    __shared__ float Rs[64][PAD];

    const int bm = blockIdx.x * 64;
    const int bn = blockIdx.y * 64;
    const int tid = threadIdx.x;
    const int wid = tid >> 5, lane = tid & 31;
    const int wm = (wid & 3) * 16;
    const int wn = (wid >> 2) * 32;
    const int gid = lane >> 2, tig = lane & 3;

    const int lr = tid >> 2, lk = (tid & 3) * 4;
    const int qk = tid >> 4, qn = (tid & 15) * 4;

    float acc[4][4];
#pragma unroll
    for (int j = 0; j < 4; j++)
#pragma unroll
        for (int r = 0; r < 4; r++) acc[j][r] = 0.f;

    float4 uv = *(const float4*)(Uh + (size_t)(bm + lr) * F + lk);
    float4 rv = *(const float4*)(rq + (size_t)qk * F + bn + qn);

    for (int t16 = 0; t16 < 16; t16++) {
        *(float4*)&Us[lr][lk] = uv;
        Rs[qn][qk] = rv.x; Rs[qn + 1][qk] = rv.y;
        Rs[qn + 2][qk] = rv.z; Rs[qn + 3][qk] = rv.w;
        __syncthreads();
        if (t16 < 15) {
            const int k0 = (t16 + 1) * 16;
            uv = *(const float4*)(Uh + (size_t)(bm + lr) * F + k0 + lk);
            rv = *(const float4*)(rq + (size_t)(k0 + qk) * F + bn + qn);
        }
#pragma unroll
        for (int ks = 0; ks < 2; ks++) {
            const int kb = ks * 8;
            uint32_t ahi[4], alo[4];
            split2(Us[wm + gid][kb + tig], ahi[0], alo[0]);
            split2(Us[wm + gid + 8][kb + tig], ahi[1], alo[1]);
            split2(Us[wm + gid][kb + tig + 4], ahi[2], alo[2]);
            split2(Us[wm + gid + 8][kb + tig + 4], ahi[3], alo[3]);
            uint32_t bhi[4][2], blo[4][2];
#pragma unroll
            for (int nf = 0; nf < 4; nf++) {
                const int n = wn + nf * 8 + gid;
                split2(Rs[n][kb + tig], bhi[nf][0], blo[nf][0]);
                split2(Rs[n][kb + tig + 4], bhi[nf][1], blo[nf][1]);
            }
#pragma unroll
            for (int nf = 0; nf < 4; nf++) {
                mma_tf32(acc[nf], ahi, bhi[nf]);
                mma_tf32(acc[nf], ahi, blo[nf]);
                mma_tf32(acc[nf], alo, bhi[nf]);
            }
        }
        __syncthreads();
    }

#pragma unroll
    for (int nf = 0; nf < 4; nf++) {
        const int row = bm + wm + gid;
        const int col = bn + wn + nf * 8 + tig * 2;
#pragma unroll
        for (int half = 0; half < 2; half++) {
            const int r = row + half * 8;
#pragma unroll
            for (int j = 0; j < 2; j++) {
                const size_t idx = (size_t)r * F + col + j;
                float hc = tanhf(acc[nf][half * 2 + j] + whz[idx]);
                float u_ = upd[idx];
                Qout[idx] = (1.f - u_) * Q[idx] + u_ * hc;
            }
        }
    }
}

// ---------------- Xt[t][f][n] = X[t][n][f]  (grid: (128, 8, 7), block 256) ----
__global__ void __launch_bounds__(256) transpose_kernel(const float* __restrict__ X,
                                                        float* __restrict__ Xt) {
    __shared__ float ts[32][33];
    const int t = blockIdx.z;
    const int nb = blockIdx.x * 32;
    const int fb = blockIdx.y * 32;
    const int tx = threadIdx.x & 31, ty = threadIdx.x >> 5;
    const float* src = X + (size_t)t * NN * F;
    float* dst = Xt + (size_t)t * F * NN;
#pragma unroll
    for (int j = 0; j < 32; j += 8)
        ts[ty + j][tx] = src[(size_t)(nb + ty + j) * F + fb + tx];
    __syncthreads();
#pragma unroll
    for (int j = 0; j < 32; j += 8)
        dst[(size_t)(fb + ty + j) * NN + nb + tx] = ts[tx][ty + j];
}

// ---------------- scorer norms ----------------
__global__ void __launch_bounds__(256) sn_kernel(const float* __restrict__ s0,
                                                 const float* __restrict__ s1) {
    const float* s = (blockIdx.x == 0) ? s0 : s1;
    float p = s[threadIdx.x];
    p = p * p;
#pragma unroll
    for (int o = 16; o > 0; o >>= 1) p += __shfl_xor_sync(0xffffffffu, p, o);
    __shared__ float ws[8];
    if ((threadIdx.x & 31) == 0) ws[threadIdx.x >> 5] = p;
    __syncthreads();
    if (threadIdx.x == 0) {
        float sum = 0.f;
#pragma unroll
        for (int i = 0; i < 8; i++) sum += ws[i];
        g_sn[blockIdx.x] = sqrtf(sum);
    }
}

// ---------------- tval[row] = tanh((E[row,:] . scorer) / sn), rows 0..255 -----
__global__ void __launch_bounds__(256) tval_kernel(const float* __restrict__ Ebase,
                                                   size_t tstride,
                                                   const float* __restrict__ scorer,
                                                   int layer, float* __restrict__ out) {
    const float* E = Ebase + (size_t)blockIdx.y * tstride;
    const int wid = threadIdx.x >> 5, lane = threadIdx.x & 31;
    const int row = blockIdx.x * 8 + wid;
    float p = 0.f;
#pragma unroll
    for (int c = lane; c < F; c += 32) p += E[(size_t)row * F + c] * scorer[c];
#pragma unroll
    for (int o = 16; o > 0; o >>= 1) p += __shfl_xor_sync(0xffffffffu, p, o);
    if (lane == 0) out[(size_t)blockIdx.y * F + row] = tanhf(p / g_sn[layer]);
}

// ---------------- prep1: h_top = relu(P @ Q0), write E + tval (layer 1) ------
__global__ void __launch_bounds__(256) prep1_kernel(const float* __restrict__ P,
                                                    const float* __restrict__ Q0,
                                                    const float* __restrict__ scorer,
                                                    float* __restrict__ Eout,
                                                    float* __restrict__ tvout) {
    __shared__ float ps[4][F];
    __shared__ float red[4][8];
    const int tid = threadIdx.x;
    const int r0 = blockIdx.x * 4;
#pragma unroll
    for (int r = 0; r < 4; r++) ps[r][tid] = P[(size_t)(r0 + r) * F + tid];
    __syncthreads();
    float a0 = 0.f, a1 = 0.f, a2 = 0.f, a3 = 0.f;
#pragma unroll 8
    for (int k = 0; k < F; k++) {
        float qv = Q0[(size_t)k * F + tid];
        a0 += ps[0][k] * qv; a1 += ps[1][k] * qv;
        a2 += ps[2][k] * qv; a3 += ps[3][k] * qv;
    }
    a0 = fmaxf(a0, 0.f); a1 = fmaxf(a1, 0.f);
    a2 = fmaxf(a2, 0.f); a3 = fmaxf(a3, 0.f);
    Eout[(size_t)(r0 + 0) * F + tid] = a0;
    Eout[(size_t)(r0 + 1) * F + tid] = a1;
    Eout[(size_t)(r0 + 2) * F + tid] = a2;
    Eout[(size_t)(r0 + 3) * F + tid] = a3;
    const float sc = scorer[tid];
    float p[4] = {a0 * sc, a1 * sc, a2 * sc, a3 * sc};
    const int wid = tid >> 5, lane = tid & 31;
#pragma unroll
    for (int r = 0; r < 4; r++) {
#pragma unroll
        for (int o = 16; o > 0; o >>= 1) p[r] += __shfl_xor_sync(0xffffffffu, p[r], o);
        if (lane == 0) red[r][wid] = p[r];
    }
    __syncthreads();
    if (tid < 4) {
        float s = 0.f;
#pragma unroll
        for (int i = 0; i < 8; i++) s += red[tid][i];
        tvout[r0 + tid] = tanhf(s / g_sn[1]);
    }
}

// ---------------- generic SGEMM: C = [relu](A @ B), optional transposed store --
__global__ void __launch_bounds__(256) sgemm_kernel(const float* __restrict__ A,
                                                    const float* __restrict__ B,
                                                    float* __restrict__ C,
                                                    int M, int N, int K, int do_relu,
                                                    int transC, int ldc) {
    __shared__ float As[16][128];
    __shared__ float Bs[16][64];
    const int bm = blockIdx.y * 128;
    const int bn = blockIdx.x * 64;
    const int tid = threadIdx.x;
    const int tx = tid & 15;
    const int ty = tid >> 4;

    float acc[8][4];
#pragma unroll
    for (int i = 0; i < 8; i++)
#pragma unroll
        for (int j = 0; j < 4; j++) acc[i][j] = 0.f;

    const int arow0 = tid >> 2;
    const int akk = (tid & 3) << 2;
    const int brow = tid >> 4;
    const int bnn = (tid & 15) << 2;

    for (int k0 = 0; k0 < K; k0 += 16) {
#pragma unroll
        for (int i = 0; i < 2; i++) {
            const int row = arow0 + i * 64;
            float4 v = *(const float4*)(A + (size_t)(bm + row) * K + (k0 + akk));
            As[akk + 0][row] = v.x;
            As[akk + 1][row] = v.y;
            As[akk + 2][row] = v.z;
            As[akk + 3][row] = v.w;
        }
        {
            float4 v = *(const float4*)(B + (size_t)(k0 + brow) * N + (bn + bnn));
            *(float4*)(&Bs[brow][bnn]) = v;
        }
        __syncthreads();
#pragma unroll
        for (int k = 0; k < 16; k++) {
            float4 a0 = *(const float4*)(&As[k][ty * 8]);
            float4 a1 = *(const float4*)(&As[k][ty * 8 + 4]);
            float4 bv = *(const float4*)(&Bs[k][tx * 4]);
            float a[8] = {a0.x, a0.y, a0.z, a0.w, a1.x, a1.y, a1.z, a1.w};
            float b[4] = {bv.x, bv.y, bv.z, bv.w};
#pragma unroll
            for (int i = 0; i < 8; i++)
#pragma unroll
                for (int j = 0; j < 4; j++) acc[i][j] += a[i] * b[j];
        }
        __syncthreads();
    }
    if (!transC) {
#pragma unroll
        for (int i = 0; i < 8; i++) {
            float4 v;
            v.x = acc[i][0]; v.y = acc[i][1]; v.z = acc[i][2]; v.w = acc[i][3];
            if (do_relu) {
                v.x = fmaxf(v.x, 0.f); v.y = fmaxf(v.y, 0.f);
                v.z = fmaxf(v.z, 0.f); v.w = fmaxf(v.w, 0.f);
            }
            *(float4*)(C + (size_t)(bm + ty * 8 + i) * ldc + bn + tx * 4) = v;
        }
    } else {
#pragma unroll
        for (int j = 0; j < 4; j++) {
            float4 v0, v1;
            v0.x = acc[0][j]; v0.y = acc[1][j]; v0.z = acc[2][j]; v0.w = acc[3][j];
            v1.x = acc[4][j]; v1.y = acc[5][j]; v1.z = acc[6][j]; v1.w = acc[7][j];
            if (do_relu) {
                v0.x = fmaxf(v0.x, 0.f); v0.y = fmaxf(v0.y, 0.f);
                v0.z = fmaxf(v0.z, 0.f); v0.w = fmaxf(v0.w, 0.f);
                v1.x = fmaxf(v1.x, 0.f); v1.y = fmaxf(v1.y, 0.f);
                v1.z = fmaxf(v1.z, 0.f); v1.w = fmaxf(v1.w, 0.f);
            }
            float* Cp = C + (size_t)(bn + tx * 4 + j) * ldc + bm + ty * 8;
            *(float4*)(Cp) = v0;
            *(float4*)(Cp + 4) = v1;
        }
    }
}

// ---------------- orchestration ----------------
extern "C" void kernel_launch(void* const* d_in, const int* in_sizes, int n_in,
                              void* d_out, int out_size) {
    const float* in[25];
    for (int i = 0; i < 25; i++) in[i] = (const float*)d_in[i];
    const float* A = in[0];
    const float* X = in[1];
    // 3: l0_scorer, 4..13: l0 Wz Uz bz Wr Ur br Wh Uh bh Q0
    // 14: l1_scorer, 15..24: l1 Wz Uz bz Wr Ur br Wh Uh bh Q0

    float *Qb, *Pb, *Eb, *tv0, *tv1, *updb, *rqb, *whzb, *Yt, *h1, *Xt;
    cudaGetSymbolAddress((void**)&Qb, g_Q);
    cudaGetSymbolAddress((void**)&Pb, g_P);
    cudaGetSymbolAddress((void**)&Eb, g_E);
    cudaGetSymbolAddress((void**)&tv0, g_tv0);
    cudaGetSymbolAddress((void**)&tv1, g_tv);
    cudaGetSymbolAddress((void**)&updb, g_upd);
    cudaGetSymbolAddress((void**)&rqb, g_rq);
    cudaGetSymbolAddress((void**)&whzb, g_whz);
    cudaGetSymbolAddress((void**)&Yt, g_Yt);
    cudaGetSymbolAddress((void**)&h1, g_h1);
    cudaGetSymbolAddress((void**)&Xt, g_Xt);

    sn_kernel<<<2, 256>>>(in[3], in[14]);
    transpose_kernel<<<dim3(128, 8, 7), 256>>>(X, Xt);
    tf32_gemm_kernel<<<dim3(4, 2, 7), 256>>>(A, (size_t)NN * NN, Xt, (size_t)F * NN,
                                             Pb, (size_t)F * F, NN, 0);
    tval_kernel<<<dim3(32, TT), 256>>>(X, (size_t)NN * F, in[3], 0, tv0);

    for (int t = 0; t < TT; t++) {
        const float* embs0 = X + (size_t)t * NN * F;
        const float* q0in = (t == 0) ? in[13] : Qb + (size_t)(0 * 2 + ((t - 1) & 1)) * F * F;
        float* q0out = Qb + (size_t)(0 * 2 + (t & 1)) * F * F;
        const float* q1in = (t == 0) ? in[24] : Qb + (size_t)(2 + ((t - 1) & 1)) * F * F;
        float* q1out = Qb + (size_t)(2 + (t & 1)) * F * F;

        // ---- layer 0 GRU (tensor) ----
        stage1_tc<<<dim3(4, 4, 3), 256>>>(in[4], in[5], in[6], in[7], in[8], in[9],
                                          in[10], in[12], embs0, tv0 + t * F, q0in,
                                          updb, rqb, whzb);
        stage2_tc<<<dim3(4, 4), 256>>>(in[11], q0in, rqb, updb, whzb, q0out);

        if (t < TT - 1) {
            prep1_kernel<<<64, 256>>>(Pb + (size_t)t * F * F, q0out, in[14], Eb, tv1);
            stage1_tc<<<dim3(4, 4, 3), 256>>>(in[15], in[16], in[17], in[18], in[19],
                                              in[20], in[21], in[23], Eb, tv1, q1in,
                                              updb, rqb, whzb);
            stage2_tc<<<dim3(4, 4), 256>>>(in[22], q1in, rqb, updb, whzb, q1out);
        } else {
            const float* At = A + (size_t)t * NN * NN;
            // Y0t = (X7 @ Q0)^T  [256, 4096]
            sgemm_kernel<<<dim3(4, 32), 256>>>(embs0, q0out, Yt, NN, F, F, 0, 1, NN);
            // h1 = relu(A7 @ Y0)
            tf32_gemm_kernel<<<dim3(4, 32, 1), 256>>>(At, 0, Yt, 0, h1, 0, NN, 1);
            // layer-1 GRU from h1
            tval_kernel<<<dim3(32, 1), 256>>>(h1, 0, in[14], 1, tv1);
            stage1_tc<<<dim3(4, 4, 3), 256>>>(in[15], in[16], in[17], in[18], in[19],
                                              in[20], in[21], in[23], h1, tv1, q1in,
                                              updb, rqb, whzb);
            stage2_tc<<<dim3(4, 4), 256>>>(in[22], q1in, rqb, updb, whzb, q1out);
            // Y1t = (h1 @ Q1)^T, out = relu(A7 @ Y1)
            sgemm_kernel<<<dim3(4, 32), 256>>>(h1, q1out, Yt, NN, F, F, 0, 1, NN);
            tf32_gemm_kernel<<<dim3(4, 32, 1), 256>>>(At, 0, Yt, 0, (float*)d_out, 0, NN, 1);
        }
    }
}

// round 10
// speedup vs baseline: 1.3660x; 1.3660x over previous
#include <cuda_runtime.h>
#include <math.h>
#include <stdint.h>

#define F 256
#define NN 4096
#define TT 8

// ---------------- scratch (no allocations allowed) ----------------
__device__ float g_sn[2];
__device__ float g_Q0h[TT * F * F];    // layer-0 Q history (after step t)
__device__ float g_Q1[2 * F * F];      // layer-1 Q ping-pong
__device__ float g_P[7 * F * F];       // P[t] = A[t][0:256,:] @ X[t]
__device__ float g_E1[7 * F * F];      // layer-1 h_top for t=0..6
__device__ float g_tv0[TT * F];        // layer-0 tanh(score) for all t
__device__ float g_tv1[7 * F];         // layer-1 tanh(score) for t=0..6
__device__ float g_tvT[F];             // layer-1 tanh(score) at t=7
__device__ float g_upd[F * F];
__device__ float g_rq[F * F];
__device__ float g_whz[F * F];
__device__ float g_Y[NN * F];
__device__ float g_h1[NN * F];

// =================== tf32 split helpers ===================
__device__ __forceinline__ void split2(float v, uint32_t& hi, uint32_t& lo) {
    uint32_t u = __float_as_uint(v) & 0xffffe000u;
    hi = u;
    lo = __float_as_uint(v - __uint_as_float(u));
}

__device__ __forceinline__ void mma_tf32(float* d, const uint32_t* a, const uint32_t* b) {
    asm volatile(
        "mma.sync.aligned.m16n8k8.row.col.f32.tf32.tf32.f32 "
        "{%0,%1,%2,%3}, {%4,%5,%6,%7}, {%8,%9}, {%0,%1,%2,%3};\n"
        : "+f"(d[0]), "+f"(d[1]), "+f"(d[2]), "+f"(d[3])
        : "r"(a[0]), "r"(a[1]), "r"(a[2]), "r"(a[3]), "r"(b[0]), "r"(b[1]));
}

// ====== tf32 3x-split GEMM (NN): C[M,256] = [relu](A[M,K] @ B[K,256]) =========
// A row-major lda=K; B row-major ldb=256. CTA tile 128x64, kc=16, 8 warps.
// Batched over blockIdx.z via element strides.
__global__ void __launch_bounds__(256) tf32_nn_kernel(
    const float* __restrict__ A, size_t strideA,
    const float* __restrict__ B, size_t strideB,
    float* __restrict__ C, size_t strideC,
    int K, int do_relu) {
    __shared__ float As[2][128][20];
    __shared__ float Bs[2][16][68];

    const float* Ap = A + strideA * blockIdx.z;
    const float* Bp = B + strideB * blockIdx.z;
    float* Cp = C + strideC * blockIdx.z;

    const int bm = blockIdx.y * 128;
    const int bn = blockIdx.x * 64;
    const int tid = threadIdx.x;
    const int wid = tid >> 5, lane = tid & 31;
    const int wm = (wid & 3) * 32;
    const int wn = (wid >> 2) * 32;
    const int gid = lane >> 2, tig = lane & 3;

    const int ar = tid >> 1, ak = (tid & 1) * 8;   // A: 128 rows x 16 k
    const int br = tid >> 4, bc = (tid & 15) * 4;  // B: 16 k-rows x 64 cols

    float acc[2][4][4];
#pragma unroll
    for (int i = 0; i < 2; i++)
#pragma unroll
        for (int j = 0; j < 4; j++)
#pragma unroll
            for (int r = 0; r < 4; r++) acc[i][j][r] = 0.f;

    const int ntiles = K >> 4;

    float4 a0v = *(const float4*)(Ap + (size_t)(bm + ar) * K + ak);
    float4 a1v = *(const float4*)(Ap + (size_t)(bm + ar) * K + ak + 4);
    float4 bv = *(const float4*)(Bp + (size_t)br * F + bn + bc);
    *(float4*)&As[0][ar][ak] = a0v;
    *(float4*)&As[0][ar][ak + 4] = a1v;
    *(float4*)&Bs[0][br][bc] = bv;
    __syncthreads();

    for (int tile = 0; tile < ntiles; tile++) {
        const int buf = tile & 1;
        if (tile + 1 < ntiles) {
            const int k0 = (tile + 1) << 4;
            a0v = *(const float4*)(Ap + (size_t)(bm + ar) * K + k0 + ak);
            a1v = *(const float4*)(Ap + (size_t)(bm + ar) * K + k0 + ak + 4);
            bv = *(const float4*)(Bp + (size_t)(k0 + br) * F + bn + bc);
        }
#pragma unroll
        for (int ks = 0; ks < 2; ks++) {
            const int kb = ks * 8;
            uint32_t ahi[2][4], alo[2][4];
#pragma unroll
            for (int mf = 0; mf < 2; mf++) {
                const int r = wm + mf * 16 + gid;
                split2(As[buf][r][kb + tig], ahi[mf][0], alo[mf][0]);
                split2(As[buf][r + 8][kb + tig], ahi[mf][1], alo[mf][1]);
                split2(As[buf][r][kb + tig + 4], ahi[mf][2], alo[mf][2]);
                split2(As[buf][r + 8][kb + tig + 4], ahi[mf][3], alo[mf][3]);
            }
            uint32_t bhi[4][2], blo[4][2];
#pragma unroll
            for (int nf = 0; nf < 4; nf++) {
                const int n = wn + nf * 8 + gid;
                split2(Bs[buf][kb + tig][n], bhi[nf][0], blo[nf][0]);
                split2(Bs[buf][kb + tig + 4][n], bhi[nf][1], blo[nf][1]);
            }
#pragma unroll
            for (int mf = 0; mf < 2; mf++)
#pragma unroll
                for (int nf = 0; nf < 4; nf++) {
                    mma_tf32(acc[mf][nf], ahi[mf], bhi[nf]);
                    mma_tf32(acc[mf][nf], ahi[mf], blo[nf]);
                    mma_tf32(acc[mf][nf], alo[mf], bhi[nf]);
                }
        }
        __syncthreads();
        if (tile + 1 < ntiles) {
            const int nb = (tile + 1) & 1;
            *(float4*)&As[nb][ar][ak] = a0v;
            *(float4*)&As[nb][ar][ak + 4] = a1v;
            *(float4*)&Bs[nb][br][bc] = bv;
            __syncthreads();
        }
    }

#pragma unroll
    for (int mf = 0; mf < 2; mf++)
#pragma unroll
        for (int nf = 0; nf < 4; nf++) {
            const int row = bm + wm + mf * 16 + gid;
            const int col = bn + wn + nf * 8 + tig * 2;
            float v0 = acc[mf][nf][0], v1 = acc[mf][nf][1];
            float v2 = acc[mf][nf][2], v3 = acc[mf][nf][3];
            if (do_relu) {
                v0 = fmaxf(v0, 0.f); v1 = fmaxf(v1, 0.f);
                v2 = fmaxf(v2, 0.f); v3 = fmaxf(v3, 0.f);
            }
            Cp[(size_t)row * F + col] = v0;
            Cp[(size_t)row * F + col + 1] = v1;
            Cp[(size_t)(row + 8) * F + col] = v2;
            Cp[(size_t)(row + 8) * F + col + 1] = v3;
        }
}

// ---------------- scorer norms ----------------
__global__ void __launch_bounds__(256) sn_kernel(const float* __restrict__ s0,
                                                 const float* __restrict__ s1) {
    const float* s = (blockIdx.x == 0) ? s0 : s1;
    float p = s[threadIdx.x];
    p = p * p;
#pragma unroll
    for (int o = 16; o > 0; o >>= 1) p += __shfl_xor_sync(0xffffffffu, p, o);
    __shared__ float ws[8];
    if ((threadIdx.x & 31) == 0) ws[threadIdx.x >> 5] = p;
    __syncthreads();
    if (threadIdx.x == 0) {
        float sum = 0.f;
#pragma unroll
        for (int i = 0; i < 8; i++) sum += ws[i];
        g_sn[blockIdx.x] = sqrtf(sum);
    }
}

// ---------------- tval[row] = tanh((E[row,:] . scorer) / sn), rows 0..255 -----
__global__ void __launch_bounds__(256) tval_kernel(const float* __restrict__ Ebase,
                                                   size_t tstride,
                                                   const float* __restrict__ scorer,
                                                   int layer, float* __restrict__ out) {
    const float* E = Ebase + (size_t)blockIdx.y * tstride;
    const int wid = threadIdx.x >> 5, lane = threadIdx.x & 31;
    const int row = blockIdx.x * 8 + wid;
    float p = 0.f;
#pragma unroll
    for (int c = lane; c < F; c += 32) p += E[(size_t)row * F + c] * scorer[c];
#pragma unroll
    for (int o = 16; o > 0; o >>= 1) p += __shfl_xor_sync(0xffffffffu, p, o);
    if (lane == 0) out[(size_t)blockIdx.y * F + row] = tanhf(p / g_sn[layer]);
}

// ---------------- GRU stage 1 (SIMT + register prefetch) ----------------------
// S_g[m,n] = tv[n]*(W_g @ E^T)[m,n] + (U_g @ Q)[m,n] + b_g[m,n]   (gate h: no U)
// grid (8 m, 8 n, 3 gates), 32x32 tiles, 2x2/thread
__global__ void __launch_bounds__(256) stage1_kernel(
    const float* __restrict__ Wz, const float* __restrict__ Uz, const float* __restrict__ bz,
    const float* __restrict__ Wr, const float* __restrict__ Ur, const float* __restrict__ br,
    const float* __restrict__ Wh, const float* __restrict__ bh,
    const float* __restrict__ E, const float* __restrict__ tv,
    const float* __restrict__ Q,
    float* __restrict__ upd, float* __restrict__ rq, float* __restrict__ whz) {
    const int gate = blockIdx.z;
    const float* W = (gate == 0) ? Wz : ((gate == 1) ? Wr : Wh);
    const float* U = (gate == 0) ? Uz : Ur;
    const float* bias = (gate == 0) ? bz : ((gate == 1) ? br : bh);

    __shared__ float Ws[32][17];
    __shared__ float Es[32][17];
    __shared__ float Us[32][17];
    __shared__ float Qs[16][32];

    const int bm = blockIdx.x * 32;
    const int bn = blockIdx.y * 32;
    const int tid = threadIdx.x;
    const int tx = tid & 15, ty = tid >> 4;
    const int m0 = ty * 2, n0 = tx * 2;

    const int lrow = tid >> 3;
    const int lkk = (tid & 7) * 2;
    const int qk = tid >> 4;
    const int qn = (tid & 15) * 2;

    float nt00 = 0.f, nt01 = 0.f, nt10 = 0.f, nt11 = 0.f;
    float nn00 = 0.f, nn01 = 0.f, nn10 = 0.f, nn11 = 0.f;

    float2 wv = *(const float2*)(W + (size_t)(bm + lrow) * F + lkk);
    float2 ev = *(const float2*)(E + (size_t)(bn + lrow) * F + lkk);
    float2 uv = {0.f, 0.f}, qv = {0.f, 0.f};
    if (gate < 2) {
        uv = *(const float2*)(U + (size_t)(bm + lrow) * F + lkk);
        qv = *(const float2*)(Q + (size_t)qk * F + bn + qn);
    }

    for (int kt = 0; kt < 16; kt++) {
        Ws[lrow][lkk] = wv.x; Ws[lrow][lkk + 1] = wv.y;
        Es[lrow][lkk] = ev.x; Es[lrow][lkk + 1] = ev.y;
        if (gate < 2) {
            Us[lrow][lkk] = uv.x; Us[lrow][lkk + 1] = uv.y;
            Qs[qk][qn] = qv.x; Qs[qk][qn + 1] = qv.y;
        }
        __syncthreads();
        if (kt < 15) {
            const int k0 = (kt + 1) * 16;
            wv = *(const float2*)(W + (size_t)(bm + lrow) * F + k0 + lkk);
            ev = *(const float2*)(E + (size_t)(bn + lrow) * F + k0 + lkk);
            if (gate < 2) {
                uv = *(const float2*)(U + (size_t)(bm + lrow) * F + k0 + lkk);
                qv = *(const float2*)(Q + (size_t)(k0 + qk) * F + bn + qn);
            }
        }
        if (gate < 2) {
#pragma unroll
            for (int k = 0; k < 16; k++) {
                float w0 = Ws[m0][k], w1 = Ws[m0 + 1][k];
                float e0 = Es[n0][k], e1 = Es[n0 + 1][k];
                float u0 = Us[m0][k], u1 = Us[m0 + 1][k];
                float q0 = Qs[k][n0], q1 = Qs[k][n0 + 1];
                nt00 += w0 * e0; nt01 += w0 * e1;
                nt10 += w1 * e0; nt11 += w1 * e1;
                nn00 += u0 * q0; nn01 += u0 * q1;
                nn10 += u1 * q0; nn11 += u1 * q1;
            }
        } else {
#pragma unroll
            for (int k = 0; k < 16; k++) {
                float w0 = Ws[m0][k], w1 = Ws[m0 + 1][k];
                float e0 = Es[n0][k], e1 = Es[n0 + 1][k];
                nt00 += w0 * e0; nt01 += w0 * e1;
                nt10 += w1 * e0; nt11 += w1 * e1;
            }
        }
        __syncthreads();
    }

    const float tv0 = tv[bn + n0], tv1 = tv[bn + n0 + 1];
    float S[2][2];
    S[0][0] = tv0 * nt00 + nn00; S[0][1] = tv1 * nt01 + nn01;
    S[1][0] = tv0 * nt10 + nn10; S[1][1] = tv1 * nt11 + nn11;
#pragma unroll
    for (int i = 0; i < 2; i++)
#pragma unroll
        for (int j = 0; j < 2; j++) {
            const size_t idx = (size_t)(bm + m0 + i) * F + bn + n0 + j;
            float v = S[i][j] + bias[idx];
            if (gate == 0) {
                upd[idx] = 1.f / (1.f + expf(-v));
            } else if (gate == 1) {
                rq[idx] = (1.f / (1.f + expf(-v))) * Q[idx];
            } else {
                whz[idx] = v;
            }
        }
}

// ---------------- GRU stage 2 (SIMT + register prefetch) ----------------------
// Qn = (1-u)Q + u*tanh(whz + Uh@rq), grid (8,8), 32x32 tiles
__global__ void __launch_bounds__(256) stage2_kernel(
    const float* __restrict__ Uh, const float* __restrict__ Q,
    const float* __restrict__ rq, const float* __restrict__ upd,
    const float* __restrict__ whz, float* __restrict__ Qout) {
    __shared__ float Us[32][17];
    __shared__ float Rs[16][32];
    const int bm = blockIdx.x * 32;
    const int bn = blockIdx.y * 32;
    const int tid = threadIdx.x;
    const int tx = tid & 15, ty = tid >> 4;
    const int m0 = ty * 2, n0 = tx * 2;
    const int lrow = tid >> 3;
    const int lkk = (tid & 7) * 2;
    const int qk = tid >> 4;
    const int qn = (tid & 15) * 2;

    float c00 = 0.f, c01 = 0.f, c10 = 0.f, c11 = 0.f;

    float2 uv = *(const float2*)(Uh + (size_t)(bm + lrow) * F + lkk);
    float2 rv = *(const float2*)(rq + (size_t)qk * F + bn + qn);

    for (int kt = 0; kt < 16; kt++) {
        Us[lrow][lkk] = uv.x; Us[lrow][lkk + 1] = uv.y;
        Rs[qk][qn] = rv.x; Rs[qk][qn + 1] = rv.y;
        __syncthreads();
        if (kt < 15) {
            const int k0 = (kt + 1) * 16;
            uv = *(const float2*)(Uh + (size_t)(bm + lrow) * F + k0 + lkk);
            rv = *(const float2*)(rq + (size_t)(k0 + qk) * F + bn + qn);
        }
#pragma unroll
        for (int k = 0; k < 16; k++) {
            float u0 = Us[m0][k], u1 = Us[m0 + 1][k];
            float r0 = Rs[k][n0], r1 = Rs[k][n0 + 1];
            c00 += u0 * r0; c01 += u0 * r1;
            c10 += u1 * r0; c11 += u1 * r1;
        }
        __syncthreads();
    }
    float c[2][2] = {{c00, c01}, {c10, c11}};
#pragma unroll
    for (int i = 0; i < 2; i++)
#pragma unroll
        for (int j = 0; j < 2; j++) {
            const size_t idx = (size_t)(bm + m0 + i) * F + bn + n0 + j;
            float hc = tanhf(c[i][j] + whz[idx]);
            float u_ = upd[idx];
            Qout[idx] = (1.f - u_) * Q[idx] + u_ * hc;
        }
}

// ---------------- orchestration ----------------
extern "C" void kernel_launch(void* const* d_in, const int* in_sizes, int n_in,
                              void* d_out, int out_size) {
    const float* in[25];
    for (int i = 0; i < 25; i++) in[i] = (const float*)d_in[i];
    const float* A = in[0];
    const float* X = in[1];
    // 3: l0_scorer, 4..13: l0 Wz Uz bz Wr Ur br Wh Uh bh Q0
    // 14: l1_scorer, 15..24: l1 Wz Uz bz Wr Ur br Wh Uh bh Q0

    float *q0h, *q1b, *Pb, *E1b, *tv0, *tv1, *tvT, *updb, *rqb, *whzb, *Y, *h1;
    cudaGetSymbolAddress((void**)&q0h, g_Q0h);
    cudaGetSymbolAddress((void**)&q1b, g_Q1);
    cudaGetSymbolAddress((void**)&Pb, g_P);
    cudaGetSymbolAddress((void**)&E1b, g_E1);
    cudaGetSymbolAddress((void**)&tv0, g_tv0);
    cudaGetSymbolAddress((void**)&tv1, g_tv1);
    cudaGetSymbolAddress((void**)&tvT, g_tvT);
    cudaGetSymbolAddress((void**)&updb, g_upd);
    cudaGetSymbolAddress((void**)&rqb, g_rq);
    cudaGetSymbolAddress((void**)&whzb, g_whz);
    cudaGetSymbolAddress((void**)&Y, g_Y);
    cudaGetSymbolAddress((void**)&h1, g_h1);

    const size_t FF = (size_t)F * F;

    // ---- prologue: norms, all layer-0 tvals, batched P[t] = A_t[0:256,:] @ X_t
    sn_kernel<<<2, 256>>>(in[3], in[14]);
    tval_kernel<<<dim3(32, TT), 256>>>(X, (size_t)NN * F, in[3], 0, tv0);
    tf32_nn_kernel<<<dim3(4, 2, 7), 256>>>(A, (size_t)NN * NN, X, (size_t)NN * F,
                                           Pb, FF, NN, 0);

    // ---- phase 1: layer-0 GRU chain (self-contained), store q0 history ----
    for (int t = 0; t < TT; t++) {
        const float* q0in = (t == 0) ? in[13] : q0h + (size_t)(t - 1) * FF;
        float* q0out = q0h + (size_t)t * FF;
        stage1_kernel<<<dim3(8, 8, 3), 256>>>(in[4], in[5], in[6], in[7], in[8], in[9],
                                              in[10], in[12], X + (size_t)t * NN * F,
                                              tv0 + t * F, q0in, updb, rqb, whzb);
        stage2_kernel<<<dim3(8, 8), 256>>>(in[11], q0in, rqb, updb, whzb, q0out);
    }

    // ---- phase 2: batched E1_t = relu(P_t @ q0_t), t=0..6, + batched tv1 ----
    tf32_nn_kernel<<<dim3(4, 2, 7), 256>>>(Pb, FF, q0h, FF, E1b, FF, F, 1);
    tval_kernel<<<dim3(32, 7), 256>>>(E1b, FF, in[14], 1, tv1);

    // ---- phase 3: layer-1 GRU chain t=0..6 ----
    for (int t = 0; t < 7; t++) {
        const float* q1in = (t == 0) ? in[24] : q1b + (size_t)((t - 1) & 1) * FF;
        float* q1out = q1b + (size_t)(t & 1) * FF;
        stage1_kernel<<<dim3(8, 8, 3), 256>>>(in[15], in[16], in[17], in[18], in[19],
                                              in[20], in[21], in[23], E1b + (size_t)t * FF,
                                              tv1 + t * F, q1in, updb, rqb, whzb);
        stage2_kernel<<<dim3(8, 8), 256>>>(in[22], q1in, rqb, updb, whzb, q1out);
    }

    // ---- tail (t=7): full-width GCNs + final layer-1 GRU ----
    {
        const float* X7 = X + (size_t)7 * NN * F;
        const float* A7 = A + (size_t)7 * NN * NN;
        // Y = X7 @ q0_7 ; h1 = relu(A7 @ Y)
        tf32_nn_kernel<<<dim3(4, 32, 1), 256>>>(X7, 0, q0h + 7 * FF, 0, Y, 0, F, 0);
        tf32_nn_kernel<<<dim3(4, 32, 1), 256>>>(A7, 0, Y, 0, h1, 0, NN, 1);
        // layer-1 GRU from h1
        tval_kernel<<<dim3(32, 1), 256>>>(h1, 0, in[14], 1, tvT);
        const float* q1in = q1b;                  // q1_6 lives at slot 0 (t=6)
        float* q1out = q1b + FF;
        stage1_kernel<<<dim3(8, 8, 3), 256>>>(in[15], in[16], in[17], in[18], in[19],
                                              in[20], in[21], in[23], h1, tvT, q1in,
                                              updb, rqb, whzb);
        stage2_kernel<<<dim3(8, 8), 256>>>(in[22], q1in, rqb, updb, whzb, q1out);
        // Y1 = h1 @ q1_7 ; out = relu(A7 @ Y1)
        tf32_nn_kernel<<<dim3(4, 32, 1), 256>>>(h1, 0, q1out, 0, Y, 0, F, 0);
        tf32_nn_kernel<<<dim3(4, 32, 1), 256>>>(A7, 0, Y, 0, (float*)d_out, 0, NN, 1);
    }
}

// round 15
// speedup vs baseline: 1.5416x; 1.1286x over previous
#include <cuda_runtime.h>
#include <math.h>
#include <stdint.h>

#define F 256
#define NN 4096
#define TT 8

// ---------------- scratch (no allocations allowed) ----------------
__device__ float g_sn[2];
__device__ float g_Q0h[TT * F * F];    // layer-0 Q history (after step t)
__device__ float g_Q1[2 * F * F];      // layer-1 Q ping-pong
__device__ float g_P[7 * F * F];       // P[t] = A[t][0:256,:] @ X[t]
__device__ float g_E1[7 * F * F];      // layer-1 h_top for t=0..6
__device__ float g_tv0[TT * F];        // layer-0 tanh(score) for all t
__device__ float g_tv1[7 * F];         // layer-1 tanh(score) for t=0..6
__device__ float g_tvT[F];             // layer-1 tanh(score) at t=7
__device__ float g_upd[F * F];
__device__ float g_rq[F * F];
__device__ float g_whz[F * F];
__device__ float g_Y[NN * F];
__device__ float g_h1[NN * F];

// =================== tf32 split helpers ===================
__device__ __forceinline__ void split2(float v, uint32_t& hi, uint32_t& lo) {
    uint32_t u = __float_as_uint(v) & 0xffffe000u;
    hi = u;
    lo = __float_as_uint(v - __uint_as_float(u));
}

__device__ __forceinline__ void mma_tf32(float* d, const uint32_t* a, const uint32_t* b) {
    asm volatile(
        "mma.sync.aligned.m16n8k8.row.col.f32.tf32.tf32.f32 "
        "{%0,%1,%2,%3}, {%4,%5,%6,%7}, {%8,%9}, {%0,%1,%2,%3};\n"
        : "+f"(d[0]), "+f"(d[1]), "+f"(d[2]), "+f"(d[3])
        : "r"(a[0]), "r"(a[1]), "r"(a[2]), "r"(a[3]), "r"(b[0]), "r"(b[1]));
}

// ====== tf32 3x-split GEMM (NN): C[M,256] = [relu](A[M,K] @ B[K,256]) =========
__global__ void __launch_bounds__(256) tf32_nn_kernel(
    const float* __restrict__ A, size_t strideA,
    const float* __restrict__ B, size_t strideB,
    float* __restrict__ C, size_t strideC,
    int K, int do_relu) {
    __shared__ float As[2][128][20];
    __shared__ float Bs[2][16][68];

    const float* Ap = A + strideA * blockIdx.z;
    const float* Bp = B + strideB * blockIdx.z;
    float* Cp = C + strideC * blockIdx.z;

    const int bm = blockIdx.y * 128;
    const int bn = blockIdx.x * 64;
    const int tid = threadIdx.x;
    const int wid = tid >> 5, lane = tid & 31;
    const int wm = (wid & 3) * 32;
    const int wn = (wid >> 2) * 32;
    const int gid = lane >> 2, tig = lane & 3;

    const int ar = tid >> 1, ak = (tid & 1) * 8;
    const int br = tid >> 4, bc = (tid & 15) * 4;

    float acc[2][4][4];
#pragma unroll
    for (int i = 0; i < 2; i++)
#pragma unroll
        for (int j = 0; j < 4; j++)
#pragma unroll
            for (int r = 0; r < 4; r++) acc[i][j][r] = 0.f;

    const int ntiles = K >> 4;

    float4 a0v = *(const float4*)(Ap + (size_t)(bm + ar) * K + ak);
    float4 a1v = *(const float4*)(Ap + (size_t)(bm + ar) * K + ak + 4);
    float4 bv = *(const float4*)(Bp + (size_t)br * F + bn + bc);
    *(float4*)&As[0][ar][ak] = a0v;
    *(float4*)&As[0][ar][ak + 4] = a1v;
    *(float4*)&Bs[0][br][bc] = bv;
    __syncthreads();

    for (int tile = 0; tile < ntiles; tile++) {
        const int buf = tile & 1;
        if (tile + 1 < ntiles) {
            const int k0 = (tile + 1) << 4;
            a0v = *(const float4*)(Ap + (size_t)(bm + ar) * K + k0 + ak);
            a1v = *(const float4*)(Ap + (size_t)(bm + ar) * K + k0 + ak + 4);
            bv = *(const float4*)(Bp + (size_t)(k0 + br) * F + bn + bc);
        }
#pragma unroll
        for (int ks = 0; ks < 2; ks++) {
            const int kb = ks * 8;
            uint32_t ahi[2][4], alo[2][4];
#pragma unroll
            for (int mf = 0; mf < 2; mf++) {
                const int r = wm + mf * 16 + gid;
                split2(As[buf][r][kb + tig], ahi[mf][0], alo[mf][0]);
                split2(As[buf][r + 8][kb + tig], ahi[mf][1], alo[mf][1]);
                split2(As[buf][r][kb + tig + 4], ahi[mf][2], alo[mf][2]);
                split2(As[buf][r + 8][kb + tig + 4], ahi[mf][3], alo[mf][3]);
            }
            uint32_t bhi[4][2], blo[4][2];
#pragma unroll
            for (int nf = 0; nf < 4; nf++) {
                const int n = wn + nf * 8 + gid;
                split2(Bs[buf][kb + tig][n], bhi[nf][0], blo[nf][0]);
                split2(Bs[buf][kb + tig + 4][n], bhi[nf][1], blo[nf][1]);
            }
#pragma unroll
            for (int mf = 0; mf < 2; mf++)
#pragma unroll
                for (int nf = 0; nf < 4; nf++) {
                    mma_tf32(acc[mf][nf], ahi[mf], bhi[nf]);
                    mma_tf32(acc[mf][nf], ahi[mf], blo[nf]);
                    mma_tf32(acc[mf][nf], alo[mf], bhi[nf]);
                }
        }
        __syncthreads();
        if (tile + 1 < ntiles) {
            const int nb = (tile + 1) & 1;
            *(float4*)&As[nb][ar][ak] = a0v;
            *(float4*)&As[nb][ar][ak + 4] = a1v;
            *(float4*)&Bs[nb][br][bc] = bv;
            __syncthreads();
        }
    }

#pragma unroll
    for (int mf = 0; mf < 2; mf++)
#pragma unroll
        for (int nf = 0; nf < 4; nf++) {
            const int row = bm + wm + mf * 16 + gid;
            const int col = bn + wn + nf * 8 + tig * 2;
            float v0 = acc[mf][nf][0], v1 = acc[mf][nf][1];
            float v2 = acc[mf][nf][2], v3 = acc[mf][nf][3];
            if (do_relu) {
                v0 = fmaxf(v0, 0.f); v1 = fmaxf(v1, 0.f);
                v2 = fmaxf(v2, 0.f); v3 = fmaxf(v3, 0.f);
            }
            Cp[(size_t)row * F + col] = v0;
            Cp[(size_t)row * F + col + 1] = v1;
            Cp[(size_t)(row + 8) * F + col] = v2;
            Cp[(size_t)(row + 8) * F + col + 1] = v3;
        }
}

// ---------------- scorer norms ----------------
__global__ void __launch_bounds__(256) sn_kernel(const float* __restrict__ s0,
                                                 const float* __restrict__ s1) {
    const float* s = (blockIdx.x == 0) ? s0 : s1;
    float p = s[threadIdx.x];
    p = p * p;
#pragma unroll
    for (int o = 16; o > 0; o >>= 1) p += __shfl_xor_sync(0xffffffffu, p, o);
    __shared__ float ws[8];
    if ((threadIdx.x & 31) == 0) ws[threadIdx.x >> 5] = p;
    __syncthreads();
    if (threadIdx.x == 0) {
        float sum = 0.f;
#pragma unroll
        for (int i = 0; i < 8; i++) sum += ws[i];
        g_sn[blockIdx.x] = sqrtf(sum);
    }
}

// ---------------- tval[row] = tanh((E[row,:] . scorer) / sn), rows 0..255 -----
__global__ void __launch_bounds__(256) tval_kernel(const float* __restrict__ Ebase,
                                                   size_t tstride,
                                                   const float* __restrict__ scorer,
                                                   int layer, float* __restrict__ out) {
    const float* E = Ebase + (size_t)blockIdx.y * tstride;
    const int wid = threadIdx.x >> 5, lane = threadIdx.x & 31;
    const int row = blockIdx.x * 8 + wid;
    float p = 0.f;
#pragma unroll
    for (int c = lane; c < F; c += 32) p += E[(size_t)row * F + c] * scorer[c];
#pragma unroll
    for (int o = 16; o > 0; o >>= 1) p += __shfl_xor_sync(0xffffffffu, p, o);
    if (lane == 0) out[(size_t)blockIdx.y * F + row] = tanhf(p / g_sn[layer]);
}

// ---------------- GRU stage 1 (SIMT, 4x4 micro, k-split) ----------------------
// S_g[m,n] = (W_g @ (tv*E)^T)[m,n] + (U_g @ Q)[m,n] + b_g[m,n]   (gate h: no U)
// grid (8 m, 8 n, 3 gates); 32x32 tile; 256 thr = 64 positions x 4 k-groups.
__global__ void __launch_bounds__(256) stage1_kernel(
    const float* __restrict__ Wz, const float* __restrict__ Uz, const float* __restrict__ bz,
    const float* __restrict__ Wr, const float* __restrict__ Ur, const float* __restrict__ br,
    const float* __restrict__ Wh, const float* __restrict__ bh,
    const float* __restrict__ E, const float* __restrict__ tv,
    const float* __restrict__ Q,
    float* __restrict__ upd, float* __restrict__ rq, float* __restrict__ whz) {
    const int gate = blockIdx.z;
    const float* W = (gate == 0) ? Wz : ((gate == 1) ? Wr : Wh);
    const float* U = (gate == 0) ? Uz : Ur;
    const float* bias = (gate == 0) ? bz : ((gate == 1) ? br : bh);

    __shared__ float Wk[16][36];
    __shared__ float Ek[16][36];
    __shared__ float Uk[16][36];
    __shared__ float Qk[16][36];
    __shared__ float red[4][1024];

    const int bm = blockIdx.x * 32;
    const int bn = blockIdx.y * 32;
    const int tid = threadIdx.x;
    const int kg = tid >> 6;            // k-group 0..3
    const int pos = tid & 63;
    const int m0 = (pos >> 3) * 4;      // 0..28
    const int n0 = (pos & 7) * 4;

    const int wr = tid >> 3;            // 0..31 load row
    const int wk = (tid & 7) * 2;       // 0..14 load k
    const int qk = tid >> 4;            // 0..15
    const int qn = (tid & 15) * 2;

    const float tvr = tv[bn + wr];

    float acc[4][4];
#pragma unroll
    for (int i = 0; i < 4; i++)
#pragma unroll
        for (int j = 0; j < 4; j++) acc[i][j] = 0.f;

    float2 wv = *(const float2*)(W + (size_t)(bm + wr) * F + wk);
    float2 ev = *(const float2*)(E + (size_t)(bn + wr) * F + wk);
    float2 uv = {0.f, 0.f}, qv = {0.f, 0.f};
    if (gate < 2) {
        uv = *(const float2*)(U + (size_t)(bm + wr) * F + wk);
        qv = *(const float2*)(Q + (size_t)qk * F + bn + qn);
    }

    for (int kt = 0; kt < 16; kt++) {
        Wk[wk][wr] = wv.x; Wk[wk + 1][wr] = wv.y;
        Ek[wk][wr] = ev.x * tvr; Ek[wk + 1][wr] = ev.y * tvr;
        if (gate < 2) {
            Uk[wk][wr] = uv.x; Uk[wk + 1][wr] = uv.y;
            Qk[qk][qn] = qv.x; Qk[qk][qn + 1] = qv.y;
        }
        __syncthreads();
        if (kt < 15) {
            const int k0 = (kt + 1) * 16;
            wv = *(const float2*)(W + (size_t)(bm + wr) * F + k0 + wk);
            ev = *(const float2*)(E + (size_t)(bn + wr) * F + k0 + wk);
            if (gate < 2) {
                uv = *(const float2*)(U + (size_t)(bm + wr) * F + k0 + wk);
                qv = *(const float2*)(Q + (size_t)(k0 + qk) * F + bn + qn);
            }
        }
        const int kb = kg * 4;
        if (gate < 2) {
#pragma unroll
            for (int kk = 0; kk < 4; kk++) {
                float4 a = *(const float4*)&Wk[kb + kk][m0];
                float4 b = *(const float4*)&Ek[kb + kk][n0];
                float4 a2 = *(const float4*)&Uk[kb + kk][m0];
                float4 b2 = *(const float4*)&Qk[kb + kk][n0];
                float am[4] = {a.x, a.y, a.z, a.w};
                float bm_[4] = {b.x, b.y, b.z, b.w};
                float a2m[4] = {a2.x, a2.y, a2.z, a2.w};
                float b2m[4] = {b2.x, b2.y, b2.z, b2.w};
#pragma unroll
                for (int i = 0; i < 4; i++)
#pragma unroll
                    for (int j = 0; j < 4; j++)
                        acc[i][j] += am[i] * bm_[j] + a2m[i] * b2m[j];
            }
        } else {
#pragma unroll
            for (int kk = 0; kk < 4; kk++) {
                float4 a = *(const float4*)&Wk[kb + kk][m0];
                float4 b = *(const float4*)&Ek[kb + kk][n0];
                float am[4] = {a.x, a.y, a.z, a.w};
                float bm_[4] = {b.x, b.y, b.z, b.w};
#pragma unroll
                for (int i = 0; i < 4; i++)
#pragma unroll
                    for (int j = 0; j < 4; j++)
                        acc[i][j] += am[i] * bm_[j];
            }
        }
        __syncthreads();
    }

    // k-group reduction through smem
#pragma unroll
    for (int i = 0; i < 4; i++) {
        float4 v;
        v.x = acc[i][0]; v.y = acc[i][1]; v.z = acc[i][2]; v.w = acc[i][3];
        *(float4*)&red[kg][(m0 + i) * 32 + n0] = v;
    }
    __syncthreads();

    const int m = tid >> 3;
    const int n = (tid & 7) * 4;
    const int o = m * 32 + n;
    float4 r0 = *(const float4*)&red[0][o];
    float4 r1 = *(const float4*)&red[1][o];
    float4 r2 = *(const float4*)&red[2][o];
    float4 r3 = *(const float4*)&red[3][o];
    float s[4];
    s[0] = r0.x + r1.x + r2.x + r3.x;
    s[1] = r0.y + r1.y + r2.y + r3.y;
    s[2] = r0.z + r1.z + r2.z + r3.z;
    s[3] = r0.w + r1.w + r2.w + r3.w;

    const size_t idx = (size_t)(bm + m) * F + bn + n;
    float4 bi = *(const float4*)(bias + idx);
    float bb[4] = {bi.x, bi.y, bi.z, bi.w};
    if (gate == 0) {
        float4 v;
        v.x = 1.f / (1.f + expf(-(s[0] + bb[0])));
        v.y = 1.f / (1.f + expf(-(s[1] + bb[1])));
        v.z = 1.f / (1.f + expf(-(s[2] + bb[2])));
        v.w = 1.f / (1.f + expf(-(s[3] + bb[3])));
        *(float4*)(upd + idx) = v;
    } else if (gate == 1) {
        float4 qg = *(const float4*)(Q + idx);
        float4 v;
        v.x = qg.x / (1.f + expf(-(s[0] + bb[0])));
        v.y = qg.y / (1.f + expf(-(s[1] + bb[1])));
        v.z = qg.z / (1.f + expf(-(s[2] + bb[2])));
        v.w = qg.w / (1.f + expf(-(s[3] + bb[3])));
        *(float4*)(rq + idx) = v;
    } else {
        float4 v;
        v.x = s[0] + bb[0]; v.y = s[1] + bb[1];
        v.z = s[2] + bb[2]; v.w = s[3] + bb[3];
        *(float4*)(whz + idx) = v;
    }
}

// ---------------- GRU stage 2 (SIMT, 4x4 micro, k-split) ----------------------
// Qn = (1-u)Q + u*tanh(whz + Uh@rq), grid (8,8), 32x32 tiles
__global__ void __launch_bounds__(256) stage2_kernel(
    const float* __restrict__ Uh, const float* __restrict__ Q,
    const float* __restrict__ rq, const float* __restrict__ upd,
    const float* __restrict__ whz, float* __restrict__ Qout) {
    __shared__ float Uk[16][36];
    __shared__ float Rk[16][36];
    __shared__ float red[4][1024];

    const int bm = blockIdx.x * 32;
    const int bn = blockIdx.y * 32;
    const int tid = threadIdx.x;
    const int kg = tid >> 6;
    const int pos = tid & 63;
    const int m0 = (pos >> 3) * 4;
    const int n0 = (pos & 7) * 4;

    const int wr = tid >> 3;
    const int wk = (tid & 7) * 2;
    const int qk = tid >> 4;
    const int qn = (tid & 15) * 2;

    float acc[4][4];
#pragma unroll
    for (int i = 0; i < 4; i++)
#pragma unroll
        for (int j = 0; j < 4; j++) acc[i][j] = 0.f;

    float2 uv = *(const float2*)(Uh + (size_t)(bm + wr) * F + wk);
    float2 rv = *(const float2*)(rq + (size_t)qk * F + bn + qn);

    for (int kt = 0; kt < 16; kt++) {
        Uk[wk][wr] = uv.x; Uk[wk + 1][wr] = uv.y;
        Rk[qk][qn] = rv.x; Rk[qk][qn + 1] = rv.y;
        __syncthreads();
        if (kt < 15) {
            const int k0 = (kt + 1) * 16;
            uv = *(const float2*)(Uh + (size_t)(bm + wr) * F + k0 + wk);
            rv = *(const float2*)(rq + (size_t)(k0 + qk) * F + bn + qn);
        }
        const int kb = kg * 4;
#pragma unroll
        for (int kk = 0; kk < 4; kk++) {
            float4 a = *(const float4*)&Uk[kb + kk][m0];
            float4 b = *(const float4*)&Rk[kb + kk][n0];
            float am[4] = {a.x, a.y, a.z, a.w};
            float bm_[4] = {b.x, b.y, b.z, b.w};
#pragma unroll
            for (int i = 0; i < 4; i++)
#pragma unroll
                for (int j = 0; j < 4; j++)
                    acc[i][j] += am[i] * bm_[j];
        }
        __syncthreads();
    }

#pragma unroll
    for (int i = 0; i < 4; i++) {
        float4 v;
        v.x = acc[i][0]; v.y = acc[i][1]; v.z = acc[i][2]; v.w = acc[i][3];
        *(float4*)&red[kg][(m0 + i) * 32 + n0] = v;
    }
    __syncthreads();

    const int m = tid >> 3;
    const int n = (tid & 7) * 4;
    const int o = m * 32 + n;
    float4 r0 = *(const float4*)&red[0][o];
    float4 r1 = *(const float4*)&red[1][o];
    float4 r2 = *(const float4*)&red[2][o];
    float4 r3 = *(const float4*)&red[3][o];
    float s[4];
    s[0] = r0.x + r1.x + r2.x + r3.x;
    s[1] = r0.y + r1.y + r2.y + r3.y;
    s[2] = r0.z + r1.z + r2.z + r3.z;
    s[3] = r0.w + r1.w + r2.w + r3.w;

    const size_t idx = (size_t)(bm + m) * F + bn + n;
    float4 wz = *(const float4*)(whz + idx);
    float4 uu = *(const float4*)(upd + idx);
    float4 qq = *(const float4*)(Q + idx);
    float4 v;
    v.x = (1.f - uu.x) * qq.x + uu.x * tanhf(s[0] + wz.x);
    v.y = (1.f - uu.y) * qq.y + uu.y * tanhf(s[1] + wz.y);
    v.z = (1.f - uu.z) * qq.z + uu.z * tanhf(s[2] + wz.z);
    v.w = (1.f - uu.w) * qq.w + uu.w * tanhf(s[3] + wz.w);
    *(float4*)(Qout + idx) = v;
}

// ---------------- orchestration ----------------
extern "C" void kernel_launch(void* const* d_in, const int* in_sizes, int n_in,
                              void* d_out, int out_size) {
    const float* in[25];
    for (int i = 0; i < 25; i++) in[i] = (const float*)d_in[i];
    const float* A = in[0];
    const float* X = in[1];
    // 3: l0_scorer, 4..13: l0 Wz Uz bz Wr Ur br Wh Uh bh Q0
    // 14: l1_scorer, 15..24: l1 Wz Uz bz Wr Ur br Wh Uh bh Q0

    float *q0h, *q1b, *Pb, *E1b, *tv0, *tv1, *tvT, *updb, *rqb, *whzb, *Y, *h1;
    cudaGetSymbolAddress((void**)&q0h, g_Q0h);
    cudaGetSymbolAddress((void**)&q1b, g_Q1);
    cudaGetSymbolAddress((void**)&Pb, g_P);
    cudaGetSymbolAddress((void**)&E1b, g_E1);
    cudaGetSymbolAddress((void**)&tv0, g_tv0);
    cudaGetSymbolAddress((void**)&tv1, g_tv1);
    cudaGetSymbolAddress((void**)&tvT, g_tvT);
    cudaGetSymbolAddress((void**)&updb, g_upd);
    cudaGetSymbolAddress((void**)&rqb, g_rq);
    cudaGetSymbolAddress((void**)&whzb, g_whz);
    cudaGetSymbolAddress((void**)&Y, g_Y);
    cudaGetSymbolAddress((void**)&h1, g_h1);

    const size_t FF = (size_t)F * F;

    // ---- prologue: norms, all layer-0 tvals, batched P[t] = A_t[0:256,:] @ X_t
    sn_kernel<<<2, 256>>>(in[3], in[14]);
    tval_kernel<<<dim3(32, TT), 256>>>(X, (size_t)NN * F, in[3], 0, tv0);
    tf32_nn_kernel<<<dim3(4, 2, 7), 256>>>(A, (size_t)NN * NN, X, (size_t)NN * F,
                                           Pb, FF, NN, 0);

    // ---- phase 1: layer-0 GRU chain (self-contained), store q0 history ----
    for (int t = 0; t < TT; t++) {
        const float* q0in = (t == 0) ? in[13] : q0h + (size_t)(t - 1) * FF;
        float* q0out = q0h + (size_t)t * FF;
        stage1_kernel<<<dim3(8, 8, 3), 256>>>(in[4], in[5], in[6], in[7], in[8], in[9],
                                              in[10], in[12], X + (size_t)t * NN * F,
                                              tv0 + t * F, q0in, updb, rqb, whzb);
        stage2_kernel<<<dim3(8, 8), 256>>>(in[11], q0in, rqb, updb, whzb, q0out);
    }

    // ---- phase 2: batched E1_t = relu(P_t @ q0_t), t=0..6, + batched tv1 ----
    tf32_nn_kernel<<<dim3(4, 2, 7), 256>>>(Pb, FF, q0h, FF, E1b, FF, F, 1);
    tval_kernel<<<dim3(32, 7), 256>>>(E1b, FF, in[14], 1, tv1);

    // ---- phase 3: layer-1 GRU chain t=0..6 ----
    for (int t = 0; t < 7; t++) {
        const float* q1in = (t == 0) ? in[24] : q1b + (size_t)((t - 1) & 1) * FF;
        float* q1out = q1b + (size_t)(t & 1) * FF;
        stage1_kernel<<<dim3(8, 8, 3), 256>>>(in[15], in[16], in[17], in[18], in[19],
                                              in[20], in[21], in[23], E1b + (size_t)t * FF,
                                              tv1 + t * F, q1in, updb, rqb, whzb);
        stage2_kernel<<<dim3(8, 8), 256>>>(in[22], q1in, rqb, updb, whzb, q1out);
    }

    // ---- tail (t=7): full-width GCNs + final layer-1 GRU ----
    {
        const float* X7 = X + (size_t)7 * NN * F;
        const float* A7 = A + (size_t)7 * NN * NN;
        // Y = X7 @ q0_7 ; h1 = relu(A7 @ Y)
        tf32_nn_kernel<<<dim3(4, 32, 1), 256>>>(X7, 0, q0h + 7 * FF, 0, Y, 0, F, 0);
        tf32_nn_kernel<<<dim3(4, 32, 1), 256>>>(A7, 0, Y, 0, h1, 0, NN, 1);
        // layer-1 GRU from h1
        tval_kernel<<<dim3(32, 1), 256>>>(h1, 0, in[14], 1, tvT);
        const float* q1in = q1b;                  // q1_6 lives at slot 0 (t=6)
        float* q1out = q1b + FF;
        stage1_kernel<<<dim3(8, 8, 3), 256>>>(in[15], in[16], in[17], in[18], in[19],
                                              in[20], in[21], in[23], h1, tvT, q1in,
                                              updb, rqb, whzb);
        stage2_kernel<<<dim3(8, 8), 256>>>(in[22], q1in, rqb, updb, whzb, q1out);
        // Y1 = h1 @ q1_7 ; out = relu(A7 @ Y1)
        tf32_nn_kernel<<<dim3(4, 32, 1), 256>>>(h1, 0, q1out, 0, Y, 0, F, 0);
        tf32_nn_kernel<<<dim3(4, 32, 1), 256>>>(A7, 0, Y, 0, (float*)d_out, 0, NN, 1);
    }
}

// round 17
// speedup vs baseline: 1.5423x; 1.0004x over previous
#include <cuda_runtime.h>
#include <math.h>
#include <stdint.h>

#define F 256
#define NN 4096
#define TT 8

// ---------------- scratch (no allocations allowed) ----------------
__device__ float g_sn[2];
__device__ float g_Q0h[TT * F * F];    // layer-0 Q history (after step t)
__device__ float g_Q1[2 * F * F];      // layer-1 Q ping-pong
__device__ float g_P[7 * F * F];       // P[t] = A[t][0:256,:] @ X[t]
__device__ float g_E1[7 * F * F];      // layer-1 h_top for t=0..6
__device__ float g_tv0[TT * F];        // layer-0 tanh(score) for all t
__device__ float g_tv1[7 * F];         // layer-1 tanh(score) for t=0..6
__device__ float g_tvT[F];             // layer-1 tanh(score) at t=7
__device__ float g_upd[F * F];
__device__ float g_rq[F * F];
__device__ float g_whz[F * F];
__device__ float g_Y[NN * F];
__device__ float g_h1[NN * F];

// =================== tf32 split helpers ===================
__device__ __forceinline__ void split2(float v, uint32_t& hi, uint32_t& lo) {
    uint32_t u = __float_as_uint(v) & 0xffffe000u;
    hi = u;
    lo = __float_as_uint(v - __uint_as_float(u));
}

__device__ __forceinline__ void mma_tf32(float* d, const uint32_t* a, const uint32_t* b) {
    asm volatile(
        "mma.sync.aligned.m16n8k8.row.col.f32.tf32.tf32.f32 "
        "{%0,%1,%2,%3}, {%4,%5,%6,%7}, {%8,%9}, {%0,%1,%2,%3};\n"
        : "+f"(d[0]), "+f"(d[1]), "+f"(d[2]), "+f"(d[3])
        : "r"(a[0]), "r"(a[1]), "r"(a[2]), "r"(a[3]), "r"(b[0]), "r"(b[1]));
}

// ====== tf32 3x-split GEMM (NN): C[M,256] = [relu](A[M,K] @ B[K,256]) =========
__global__ void __launch_bounds__(256) tf32_nn_kernel(
    const float* __restrict__ A, size_t strideA,
    const float* __restrict__ B, size_t strideB,
    float* __restrict__ C, size_t strideC,
    int K, int do_relu) {
    __shared__ float As[2][128][20];
    __shared__ float Bs[2][16][68];

    const float* Ap = A + strideA * blockIdx.z;
    const float* Bp = B + strideB * blockIdx.z;
    float* Cp = C + strideC * blockIdx.z;

    const int bm = blockIdx.y * 128;
    const int bn = blockIdx.x * 64;
    const int tid = threadIdx.x;
    const int wid = tid >> 5, lane = tid & 31;
    const int wm = (wid & 3) * 32;
    const int wn = (wid >> 2) * 32;
    const int gid = lane >> 2, tig = lane & 3;

    const int ar = tid >> 1, ak = (tid & 1) * 8;
    const int br = tid >> 4, bc = (tid & 15) * 4;

    float acc[2][4][4];
#pragma unroll
    for (int i = 0; i < 2; i++)
#pragma unroll
        for (int j = 0; j < 4; j++)
#pragma unroll
            for (int r = 0; r < 4; r++) acc[i][j][r] = 0.f;

    const int ntiles = K >> 4;

    float4 a0v = *(const float4*)(Ap + (size_t)(bm + ar) * K + ak);
    float4 a1v = *(const float4*)(Ap + (size_t)(bm + ar) * K + ak + 4);
    float4 bv = *(const float4*)(Bp + (size_t)br * F + bn + bc);
    *(float4*)&As[0][ar][ak] = a0v;
    *(float4*)&As[0][ar][ak + 4] = a1v;
    *(float4*)&Bs[0][br][bc] = bv;
    __syncthreads();

    for (int tile = 0; tile < ntiles; tile++) {
        const int buf = tile & 1;
        if (tile + 1 < ntiles) {
            const int k0 = (tile + 1) << 4;
            a0v = *(const float4*)(Ap + (size_t)(bm + ar) * K + k0 + ak);
            a1v = *(const float4*)(Ap + (size_t)(bm + ar) * K + k0 + ak + 4);
            bv = *(const float4*)(Bp + (size_t)(k0 + br) * F + bn + bc);
        }
#pragma unroll
        for (int ks = 0; ks < 2; ks++) {
            const int kb = ks * 8;
            uint32_t ahi[2][4], alo[2][4];
#pragma unroll
            for (int mf = 0; mf < 2; mf++) {
                const int r = wm + mf * 16 + gid;
                split2(As[buf][r][kb + tig], ahi[mf][0], alo[mf][0]);
                split2(As[buf][r + 8][kb + tig], ahi[mf][1], alo[mf][1]);
                split2(As[buf][r][kb + tig + 4], ahi[mf][2], alo[mf][2]);
                split2(As[buf][r + 8][kb + tig + 4], ahi[mf][3], alo[mf][3]);
            }
            uint32_t bhi[4][2], blo[4][2];
#pragma unroll
            for (int nf = 0; nf < 4; nf++) {
                const int n = wn + nf * 8 + gid;
                split2(Bs[buf][kb + tig][n], bhi[nf][0], blo[nf][0]);
                split2(Bs[buf][kb + tig + 4][n], bhi[nf][1], blo[nf][1]);
            }
#pragma unroll
            for (int mf = 0; mf < 2; mf++)
#pragma unroll
                for (int nf = 0; nf < 4; nf++) {
                    mma_tf32(acc[mf][nf], ahi[mf], bhi[nf]);
                    mma_tf32(acc[mf][nf], ahi[mf], blo[nf]);
                    mma_tf32(acc[mf][nf], alo[mf], bhi[nf]);
                }
        }
        __syncthreads();
        if (tile + 1 < ntiles) {
            const int nb = (tile + 1) & 1;
            *(float4*)&As[nb][ar][ak] = a0v;
            *(float4*)&As[nb][ar][ak + 4] = a1v;
            *(float4*)&Bs[nb][br][bc] = bv;
            __syncthreads();
        }
    }

#pragma unroll
    for (int mf = 0; mf < 2; mf++)
#pragma unroll
        for (int nf = 0; nf < 4; nf++) {
            const int row = bm + wm + mf * 16 + gid;
            const int col = bn + wn + nf * 8 + tig * 2;
            float v0 = acc[mf][nf][0], v1 = acc[mf][nf][1];
            float v2 = acc[mf][nf][2], v3 = acc[mf][nf][3];
            if (do_relu) {
                v0 = fmaxf(v0, 0.f); v1 = fmaxf(v1, 0.f);
                v2 = fmaxf(v2, 0.f); v3 = fmaxf(v3, 0.f);
            }
            Cp[(size_t)row * F + col] = v0;
            Cp[(size_t)row * F + col + 1] = v1;
            Cp[(size_t)(row + 8) * F + col] = v2;
            Cp[(size_t)(row + 8) * F + col + 1] = v3;
        }
}

// ---------------- scorer norms ----------------
__global__ void __launch_bounds__(256) sn_kernel(const float* __restrict__ s0,
                                                 const float* __restrict__ s1) {
    const float* s = (blockIdx.x == 0) ? s0 : s1;
    float p = s[threadIdx.x];
    p = p * p;
#pragma unroll
    for (int o = 16; o > 0; o >>= 1) p += __shfl_xor_sync(0xffffffffu, p, o);
    __shared__ float ws[8];
    if ((threadIdx.x & 31) == 0) ws[threadIdx.x >> 5] = p;
    __syncthreads();
    if (threadIdx.x == 0) {
        float sum = 0.f;
#pragma unroll
        for (int i = 0; i < 8; i++) sum += ws[i];
        g_sn[blockIdx.x] = sqrtf(sum);
    }
}

// ---------------- tval[row] = tanh((E[row,:] . scorer) / sn), rows 0..255 -----
__global__ void __launch_bounds__(256) tval_kernel(const float* __restrict__ Ebase,
                                                   size_t tstride,
                                                   const float* __restrict__ scorer,
                                                   int layer, float* __restrict__ out) {
    const float* E = Ebase + (size_t)blockIdx.y * tstride;
    const int wid = threadIdx.x >> 5, lane = threadIdx.x & 31;
    const int row = blockIdx.x * 8 + wid;
    float p = 0.f;
#pragma unroll
    for (int c = lane; c < F; c += 32) p += E[(size_t)row * F + c] * scorer[c];
#pragma unroll
    for (int o = 16; o > 0; o >>= 1) p += __shfl_xor_sync(0xffffffffu, p, o);
    if (lane == 0) out[(size_t)blockIdx.y * F + row] = tanhf(p / g_sn[layer]);
}

// ---------------- GRU stage 1 (SIMT, 4x4 micro, k-split, kc=64) ---------------
// S_g[m,n] = (W_g @ (tv*E)^T)[m,n] + (U_g @ Q)[m,n] + b_g[m,n]   (gate h: no U)
// grid (8 m, 8 n, 3 gates); 32x32 tile; 256 thr = 64 positions x 4 k-groups.
__global__ void __launch_bounds__(256) stage1_kernel(
    const float* __restrict__ Wz, const float* __restrict__ Uz, const float* __restrict__ bz,
    const float* __restrict__ Wr, const float* __restrict__ Ur, const float* __restrict__ br,
    const float* __restrict__ Wh, const float* __restrict__ bh,
    const float* __restrict__ E, const float* __restrict__ tv,
    const float* __restrict__ Q,
    float* __restrict__ upd, float* __restrict__ rq, float* __restrict__ whz) {
    const int gate = blockIdx.z;
    const float* W = (gate == 0) ? Wz : ((gate == 1) ? Wr : Wh);
    const float* U = (gate == 0) ? Uz : Ur;
    const float* bias = (gate == 0) ? bz : ((gate == 1) ? br : bh);

    __shared__ float Wk[64][36];
    __shared__ float Ek[64][36];
    __shared__ float Uk[64][36];
    __shared__ float Qk[64][36];
    __shared__ float red[4][1024];

    const int bm = blockIdx.x * 32;
    const int bn = blockIdx.y * 32;
    const int tid = threadIdx.x;
    const int kg = tid >> 6;            // k-group 0..3
    const int pos = tid & 63;
    const int m0 = (pos >> 3) * 4;      // 0..28
    const int n0 = (pos & 7) * 4;

    // strip loaders: 32 rows x 64 k, 8 k per thread
    const int wr = tid & 31;            // row
    const int wk8 = (tid >> 5) * 8;     // k offset 0..56
    // Q loader: 64 k-rows x 32 cols, 8 cols per thread
    const int qk = tid >> 2;            // 0..63
    const int qc8 = (tid & 3) * 8;      // 0,8,16,24

    const float tvr = tv[bn + wr];

    float acc[4][4];
#pragma unroll
    for (int i = 0; i < 4; i++)
#pragma unroll
        for (int j = 0; j < 4; j++) acc[i][j] = 0.f;

    float4 wv0 = *(const float4*)(W + (size_t)(bm + wr) * F + wk8);
    float4 wv1 = *(const float4*)(W + (size_t)(bm + wr) * F + wk8 + 4);
    float4 ev0 = *(const float4*)(E + (size_t)(bn + wr) * F + wk8);
    float4 ev1 = *(const float4*)(E + (size_t)(bn + wr) * F + wk8 + 4);
    float4 uv0, uv1, qv0, qv1;
    if (gate < 2) {
        uv0 = *(const float4*)(U + (size_t)(bm + wr) * F + wk8);
        uv1 = *(const float4*)(U + (size_t)(bm + wr) * F + wk8 + 4);
        qv0 = *(const float4*)(Q + (size_t)qk * F + bn + qc8);
        qv1 = *(const float4*)(Q + (size_t)qk * F + bn + qc8 + 4);
    }

#pragma unroll
    for (int ch = 0; ch < 4; ch++) {
        // store chunk to smem (k-major)
        Wk[wk8 + 0][wr] = wv0.x; Wk[wk8 + 1][wr] = wv0.y;
        Wk[wk8 + 2][wr] = wv0.z; Wk[wk8 + 3][wr] = wv0.w;
        Wk[wk8 + 4][wr] = wv1.x; Wk[wk8 + 5][wr] = wv1.y;
        Wk[wk8 + 6][wr] = wv1.z; Wk[wk8 + 7][wr] = wv1.w;
        Ek[wk8 + 0][wr] = ev0.x * tvr; Ek[wk8 + 1][wr] = ev0.y * tvr;
        Ek[wk8 + 2][wr] = ev0.z * tvr; Ek[wk8 + 3][wr] = ev0.w * tvr;
        Ek[wk8 + 4][wr] = ev1.x * tvr; Ek[wk8 + 5][wr] = ev1.y * tvr;
        Ek[wk8 + 6][wr] = ev1.z * tvr; Ek[wk8 + 7][wr] = ev1.w * tvr;
        if (gate < 2) {
            Uk[wk8 + 0][wr] = uv0.x; Uk[wk8 + 1][wr] = uv0.y;
            Uk[wk8 + 2][wr] = uv0.z; Uk[wk8 + 3][wr] = uv0.w;
            Uk[wk8 + 4][wr] = uv1.x; Uk[wk8 + 5][wr] = uv1.y;
            Uk[wk8 + 6][wr] = uv1.z; Uk[wk8 + 7][wr] = uv1.w;
            *(float4*)&Qk[qk][qc8] = qv0;
            *(float4*)&Qk[qk][qc8 + 4] = qv1;
        }
        __syncthreads();
        // prefetch next chunk
        if (ch < 3) {
            const int k0 = (ch + 1) * 64;
            wv0 = *(const float4*)(W + (size_t)(bm + wr) * F + k0 + wk8);
            wv1 = *(const float4*)(W + (size_t)(bm + wr) * F + k0 + wk8 + 4);
            ev0 = *(const float4*)(E + (size_t)(bn + wr) * F + k0 + wk8);
            ev1 = *(const float4*)(E + (size_t)(bn + wr) * F + k0 + wk8 + 4);
            if (gate < 2) {
                uv0 = *(const float4*)(U + (size_t)(bm + wr) * F + k0 + wk8);
                uv1 = *(const float4*)(U + (size_t)(bm + wr) * F + k0 + wk8 + 4);
                qv0 = *(const float4*)(Q + (size_t)(k0 + qk) * F + bn + qc8);
                qv1 = *(const float4*)(Q + (size_t)(k0 + qk) * F + bn + qc8 + 4);
            }
        }
        const int kb = kg * 16;
        if (gate < 2) {
#pragma unroll
            for (int kk = 0; kk < 16; kk++) {
                float4 a = *(const float4*)&Wk[kb + kk][m0];
                float4 b = *(const float4*)&Ek[kb + kk][n0];
                float4 a2 = *(const float4*)&Uk[kb + kk][m0];
                float4 b2 = *(const float4*)&Qk[kb + kk][n0];
                float am[4] = {a.x, a.y, a.z, a.w};
                float bm_[4] = {b.x, b.y, b.z, b.w};
                float a2m[4] = {a2.x, a2.y, a2.z, a2.w};
                float b2m[4] = {b2.x, b2.y, b2.z, b2.w};
#pragma unroll
                for (int i = 0; i < 4; i++)
#pragma unroll
                    for (int j = 0; j < 4; j++)
                        acc[i][j] += am[i] * bm_[j] + a2m[i] * b2m[j];
            }
        } else {
#pragma unroll
            for (int kk = 0; kk < 16; kk++) {
                float4 a = *(const float4*)&Wk[kb + kk][m0];
                float4 b = *(const float4*)&Ek[kb + kk][n0];
                float am[4] = {a.x, a.y, a.z, a.w};
                float bm_[4] = {b.x, b.y, b.z, b.w};
#pragma unroll
                for (int i = 0; i < 4; i++)
#pragma unroll
                    for (int j = 0; j < 4; j++)
                        acc[i][j] += am[i] * bm_[j];
            }
        }
        __syncthreads();
    }

    // k-group reduction through smem
#pragma unroll
    for (int i = 0; i < 4; i++) {
        float4 v;
        v.x = acc[i][0]; v.y = acc[i][1]; v.z = acc[i][2]; v.w = acc[i][3];
        *(float4*)&red[kg][(m0 + i) * 32 + n0] = v;
    }
    __syncthreads();

    const int m = tid >> 3;
    const int n = (tid & 7) * 4;
    const int o = m * 32 + n;
    float4 r0 = *(const float4*)&red[0][o];
    float4 r1 = *(const float4*)&red[1][o];
    float4 r2 = *(const float4*)&red[2][o];
    float4 r3 = *(const float4*)&red[3][o];
    float s[4];
    s[0] = r0.x + r1.x + r2.x + r3.x;
    s[1] = r0.y + r1.y + r2.y + r3.y;
    s[2] = r0.z + r1.z + r2.z + r3.z;
    s[3] = r0.w + r1.w + r2.w + r3.w;

    const size_t idx = (size_t)(bm + m) * F + bn + n;
    float4 bi = *(const float4*)(bias + idx);
    float bb[4] = {bi.x, bi.y, bi.z, bi.w};
    if (gate == 0) {
        float4 v;
        v.x = 1.f / (1.f + expf(-(s[0] + bb[0])));
        v.y = 1.f / (1.f + expf(-(s[1] + bb[1])));
        v.z = 1.f / (1.f + expf(-(s[2] + bb[2])));
        v.w = 1.f / (1.f + expf(-(s[3] + bb[3])));
        *(float4*)(upd + idx) = v;
    } else if (gate == 1) {
        float4 qg = *(const float4*)(Q + idx);
        float4 v;
        v.x = qg.x / (1.f + expf(-(s[0] + bb[0])));
        v.y = qg.y / (1.f + expf(-(s[1] + bb[1])));
        v.z = qg.z / (1.f + expf(-(s[2] + bb[2])));
        v.w = qg.w / (1.f + expf(-(s[3] + bb[3])));
        *(float4*)(rq + idx) = v;
    } else {
        float4 v;
        v.x = s[0] + bb[0]; v.y = s[1] + bb[1];
        v.z = s[2] + bb[2]; v.w = s[3] + bb[3];
        *(float4*)(whz + idx) = v;
    }
}

// ---------------- GRU stage 2 (SIMT, 4x4 micro, k-split, kc=64) ---------------
// Qn = (1-u)Q + u*tanh(whz + Uh@rq), grid (8,8), 32x32 tiles
__global__ void __launch_bounds__(256) stage2_kernel(
    const float* __restrict__ Uh, const float* __restrict__ Q,
    const float* __restrict__ rq, const float* __restrict__ upd,
    const float* __restrict__ whz, float* __restrict__ Qout) {
    __shared__ float Uk[64][36];
    __shared__ float Rk[64][36];
    __shared__ float red[4][1024];

    const int bm = blockIdx.x * 32;
    const int bn = blockIdx.y * 32;
    const int tid = threadIdx.x;
    const int kg = tid >> 6;
    const int pos = tid & 63;
    const int m0 = (pos >> 3) * 4;
    const int n0 = (pos & 7) * 4;

    const int wr = tid & 31;
    const int wk8 = (tid >> 5) * 8;
    const int qk = tid >> 2;
    const int qc8 = (tid & 3) * 8;

    float acc[4][4];
#pragma unroll
    for (int i = 0; i < 4; i++)
#pragma unroll
        for (int j = 0; j < 4; j++) acc[i][j] = 0.f;

    float4 uv0 = *(const float4*)(Uh + (size_t)(bm + wr) * F + wk8);
    float4 uv1 = *(const float4*)(Uh + (size_t)(bm + wr) * F + wk8 + 4);
    float4 rv0 = *(const float4*)(rq + (size_t)qk * F + bn + qc8);
    float4 rv1 = *(const float4*)(rq + (size_t)qk * F + bn + qc8 + 4);

#pragma unroll
    for (int ch = 0; ch < 4; ch++) {
        Uk[wk8 + 0][wr] = uv0.x; Uk[wk8 + 1][wr] = uv0.y;
        Uk[wk8 + 2][wr] = uv0.z; Uk[wk8 + 3][wr] = uv0.w;
        Uk[wk8 + 4][wr] = uv1.x; Uk[wk8 + 5][wr] = uv1.y;
        Uk[wk8 + 6][wr] = uv1.z; Uk[wk8 + 7][wr] = uv1.w;
        *(float4*)&Rk[qk][qc8] = rv0;
        *(float4*)&Rk[qk][qc8 + 4] = rv1;
        __syncthreads();
        if (ch < 3) {
            const int k0 = (ch + 1) * 64;
            uv0 = *(const float4*)(Uh + (size_t)(bm + wr) * F + k0 + wk8);
            uv1 = *(const float4*)(Uh + (size_t)(bm + wr) * F + k0 + wk8 + 4);
            rv0 = *(const float4*)(rq + (size_t)(k0 + qk) * F + bn + qc8);
            rv1 = *(const float4*)(rq + (size_t)(k0 + qk) * F + bn + qc8 + 4);
        }
        const int kb = kg * 16;
#pragma unroll
        for (int kk = 0; kk < 16; kk++) {
            float4 a = *(const float4*)&Uk[kb + kk][m0];
            float4 b = *(const float4*)&Rk[kb + kk][n0];
            float am[4] = {a.x, a.y, a.z, a.w};
            float bm_[4] = {b.x, b.y, b.z, b.w};
#pragma unroll
            for (int i = 0; i < 4; i++)
#pragma unroll
                for (int j = 0; j < 4; j++)
                    acc[i][j] += am[i] * bm_[j];
        }
        __syncthreads();
    }

#pragma unroll
    for (int i = 0; i < 4; i++) {
        float4 v;
        v.x = acc[i][0]; v.y = acc[i][1]; v.z = acc[i][2]; v.w = acc[i][3];
        *(float4*)&red[kg][(m0 + i) * 32 + n0] = v;
    }
    __syncthreads();

    const int m = tid >> 3;
    const int n = (tid & 7) * 4;
    const int o = m * 32 + n;
    float4 r0 = *(const float4*)&red[0][o];
    float4 r1 = *(const float4*)&red[1][o];
    float4 r2 = *(const float4*)&red[2][o];
    float4 r3 = *(const float4*)&red[3][o];
    float s[4];
    s[0] = r0.x + r1.x + r2.x + r3.x;
    s[1] = r0.y + r1.y + r2.y + r3.y;
    s[2] = r0.z + r1.z + r2.z + r3.z;
    s[3] = r0.w + r1.w + r2.w + r3.w;

    const size_t idx = (size_t)(bm + m) * F + bn + n;
    float4 wz = *(const float4*)(whz + idx);
    float4 uu = *(const float4*)(upd + idx);
    float4 qq = *(const float4*)(Q + idx);
    float4 v;
    v.x = (1.f - uu.x) * qq.x + uu.x * tanhf(s[0] + wz.x);
    v.y = (1.f - uu.y) * qq.y + uu.y * tanhf(s[1] + wz.y);
    v.z = (1.f - uu.z) * qq.z + uu.z * tanhf(s[2] + wz.z);
    v.w = (1.f - uu.w) * qq.w + uu.w * tanhf(s[3] + wz.w);
    *(float4*)(Qout + idx) = v;
}

// ---------------- orchestration ----------------
extern "C" void kernel_launch(void* const* d_in, const int* in_sizes, int n_in,
                              void* d_out, int out_size) {
    const float* in[25];
    for (int i = 0; i < 25; i++) in[i] = (const float*)d_in[i];
    const float* A = in[0];
    const float* X = in[1];
    // 3: l0_scorer, 4..13: l0 Wz Uz bz Wr Ur br Wh Uh bh Q0
    // 14: l1_scorer, 15..24: l1 Wz Uz bz Wr Ur br Wh Uh bh Q0

    float *q0h, *q1b, *Pb, *E1b, *tv0, *tv1, *tvT, *updb, *rqb, *whzb, *Y, *h1;
    cudaGetSymbolAddress((void**)&q0h, g_Q0h);
    cudaGetSymbolAddress((void**)&q1b, g_Q1);
    cudaGetSymbolAddress((void**)&Pb, g_P);
    cudaGetSymbolAddress((void**)&E1b, g_E1);
    cudaGetSymbolAddress((void**)&tv0, g_tv0);
    cudaGetSymbolAddress((void**)&tv1, g_tv1);
    cudaGetSymbolAddress((void**)&tvT, g_tvT);
    cudaGetSymbolAddress((void**)&updb, g_upd);
    cudaGetSymbolAddress((void**)&rqb, g_rq);
    cudaGetSymbolAddress((void**)&whzb, g_whz);
    cudaGetSymbolAddress((void**)&Y, g_Y);
    cudaGetSymbolAddress((void**)&h1, g_h1);

    const size_t FF = (size_t)F * F;

    // ---- prologue: norms, all layer-0 tvals, batched P[t] = A_t[0:256,:] @ X_t
    sn_kernel<<<2, 256>>>(in[3], in[14]);
    tval_kernel<<<dim3(32, TT), 256>>>(X, (size_t)NN * F, in[3], 0, tv0);
    tf32_nn_kernel<<<dim3(4, 2, 7), 256>>>(A, (size_t)NN * NN, X, (size_t)NN * F,
                                           Pb, FF, NN, 0);

    // ---- phase 1: layer-0 GRU chain (self-contained), store q0 history ----
    for (int t = 0; t < TT; t++) {
        const float* q0in = (t == 0) ? in[13] : q0h + (size_t)(t - 1) * FF;
        float* q0out = q0h + (size_t)t * FF;
        stage1_kernel<<<dim3(8, 8, 3), 256>>>(in[4], in[5], in[6], in[7], in[8], in[9],
                                              in[10], in[12], X + (size_t)t * NN * F,
                                              tv0 + t * F, q0in, updb, rqb, whzb);
        stage2_kernel<<<dim3(8, 8), 256>>>(in[11], q0in, rqb, updb, whzb, q0out);
    }

    // ---- phase 2: batched E1_t = relu(P_t @ q0_t), t=0..6, + batched tv1 ----
    tf32_nn_kernel<<<dim3(4, 2, 7), 256>>>(Pb, FF, q0h, FF, E1b, FF, F, 1);
    tval_kernel<<<dim3(32, 7), 256>>>(E1b, FF, in[14], 1, tv1);

    // ---- phase 3: layer-1 GRU chain t=0..6 ----
    for (int t = 0; t < 7; t++) {
        const float* q1in = (t == 0) ? in[24] : q1b + (size_t)((t - 1) & 1) * FF;
        float* q1out = q1b + (size_t)(t & 1) * FF;
        stage1_kernel<<<dim3(8, 8, 3), 256>>>(in[15], in[16], in[17], in[18], in[19],
                                              in[20], in[21], in[23], E1b + (size_t)t * FF,
                                              tv1 + t * F, q1in, updb, rqb, whzb);
        stage2_kernel<<<dim3(8, 8), 256>>>(in[22], q1in, rqb, updb, whzb, q1out);
    }

    // ---- tail (t=7): full-width GCNs + final layer-1 GRU ----
    {
        const float* X7 = X + (size_t)7 * NN * F;
        const float* A7 = A + (size_t)7 * NN * NN;
        // Y = X7 @ q0_7 ; h1 = relu(A7 @ Y)
        tf32_nn_kernel<<<dim3(4, 32, 1), 256>>>(X7, 0, q0h + 7 * FF, 0, Y, 0, F, 0);
        tf32_nn_kernel<<<dim3(4, 32, 1), 256>>>(A7, 0, Y, 0, h1, 0, NN, 1);
        // layer-1 GRU from h1
        tval_kernel<<<dim3(32, 1), 256>>>(h1, 0, in[14], 1, tvT);
        const float* q1in = q1b;                  // q1_6 lives at slot 0 (t=6)
        float* q1out = q1b + FF;
        stage1_kernel<<<dim3(8, 8, 3), 256>>>(in[15], in[16], in[17], in[18], in[19],
                                              in[20], in[21], in[23], h1, tvT, q1in,
                                              updb, rqb, whzb);
        stage2_kernel<<<dim3(8, 8), 256>>>(in[22], q1in, rqb, updb, whzb, q1out);
        // Y1 = h1 @ q1_7 ; out = relu(A7 @ Y1)
        tf32_nn_kernel<<<dim3(4, 32, 1), 256>>>(h1, 0, q1out, 0, Y, 0, F, 0);
        tf32_nn_kernel<<<dim3(4, 32, 1), 256>>>(A7, 0, Y, 0, (float*)d_out, 0, NN, 1);
    }
}